// round 13
// baseline (speedup 1.0000x reference)
#include <cuda_runtime.h>
#include <cuda_bf16.h>
#include <cstdint>

// Problem constants
#define NN   10000
#define NE   320000
#define F2   256     // 2*OUT

// Output layout: x_ [NN*128], s_ [NN*NN], h [NN*128]
#define S_OFF  (NN * 128)
#define H_OFF  (S_OFF + (size_t)NN * NN)

// ---------------- static device scratch (no allocs allowed) ----------------
__device__ float g_XW2[NN * F2];              // H1 @ [W2a | W2s] (fp32, gathered by agg2)
__device__ __nv_bfloat16 g_A1 [NN * 384];     // agg(h) split: [hi | lo | hi]    (K=384)
__device__ __nv_bfloat16 g_A2a[NN * 768];     // H1a split: [hi | lo | hi]       (K=768)
__device__ __nv_bfloat16 g_A2s[NN * 768];     // H1s split
__device__ __nv_bfloat16 g_WT1 [512 * 384];   // [W1a|W1s]^T split: [whi | whi | wlo]
__device__ __nv_bfloat16 g_WT2a[128 * 768];   // W2a^T split
__device__ __nv_bfloat16 g_WT2s[128 * 768];   // W2s^T split
__device__ __nv_bfloat16 g_Hb[NN * 256];      // h_ split: cols [0,128)=hi, [128,256)=lo
__device__ float g_dinv[NN];
__device__ int   g_cnt[NN];
__device__ int   g_cur[NN];
__device__ int   g_rowptr[NN + 1];
__device__ int   g_col[NE];

// ---------------- streaming-store helpers (s_ is write-once, bypass L2 retain) ----
__device__ __forceinline__ void stcs2(float* p, float x, float y) {
    asm volatile("st.global.cs.v2.f32 [%0], {%1, %2};" :: "l"(p), "f"(x), "f"(y) : "memory");
}
__device__ __forceinline__ void stcs4(float* p, float4 v) {
    asm volatile("st.global.cs.v4.f32 [%0], {%1, %2, %3, %4};"
                 :: "l"(p), "f"(v.x), "f"(v.y), "f"(v.z), "f"(v.w) : "memory");
}
__device__ __forceinline__ void stcs1(float* p, float x) {
    asm volatile("st.global.cs.f32 [%0], %1;" :: "l"(p), "f"(x) : "memory");
}

// ---------------- graph preprocessing ----------------
__global__ void k_count(const int* __restrict__ dst) {
    int e = blockIdx.x * 256 + threadIdx.x;
    if (e < NE) atomicAdd(&g_cnt[dst[e]], 1);
}

// scan cnt -> rowptr (also seeds g_cur = rowptr), AND compute dinv (fused)
__global__ void k_scan() {
    __shared__ int s[1024];
    int t = threadIdx.x;
    const int CH = 10;
    int base = t * CH;
    int sum = 0;
    #pragma unroll
    for (int i = 0; i < CH; i++) { int idx = base + i; if (idx < NN) sum += g_cnt[idx]; }
    s[t] = sum;
    __syncthreads();
    for (int off = 1; off < 1024; off <<= 1) {
        int v = (t >= off) ? s[t - off] : 0;
        __syncthreads();
        s[t] += v;
        __syncthreads();
    }
    int run = (t > 0) ? s[t - 1] : 0;
    #pragma unroll
    for (int i = 0; i < CH; i++) {
        int idx = base + i;
        if (idx < NN) {
            g_rowptr[idx] = run;
            g_cur[idx]    = run;
            int c = g_cnt[idx];
            run += c;
            g_dinv[idx] = rsqrtf(1.0f + (float)c);
        }
    }
    if (t == 1023) g_rowptr[NN] = s[1023];
}

__global__ void k_fill(const int* __restrict__ src, const int* __restrict__ dst) {
    int e = blockIdx.x * 256 + threadIdx.x;
    if (e < NE) {
        int d = dst[e];
        int pos = atomicAdd(&g_cur[d], 1);
        g_col[pos] = src[e];
    }
}

// ---------------- split helpers ----------------
struct alignas(8) bf4 { __nv_bfloat162 a, b; };

__device__ __forceinline__ void split4(float4 v, bf4& hv, bf4& lv) {
    __nv_bfloat16 h0 = __float2bfloat16(v.x), h1 = __float2bfloat16(v.y);
    __nv_bfloat16 h2 = __float2bfloat16(v.z), h3 = __float2bfloat16(v.w);
    __nv_bfloat16 l0 = __float2bfloat16(v.x - __bfloat162float(h0));
    __nv_bfloat16 l1 = __float2bfloat16(v.y - __bfloat162float(h1));
    __nv_bfloat16 l2 = __float2bfloat16(v.z - __bfloat162float(h2));
    __nv_bfloat16 l3 = __float2bfloat16(v.w - __bfloat162float(h3));
    hv.a = __nv_bfloat162(h0, h1); hv.b = __nv_bfloat162(h2, h3);
    lv.a = __nv_bfloat162(l0, l1); lv.b = __nv_bfloat162(l2, l3);
}

__device__ __forceinline__ void split2(float v0, float v1, uint32_t& hi, uint32_t& lo) {
    __nv_bfloat16 h0 = __float2bfloat16(v0), h1 = __float2bfloat16(v1);
    __nv_bfloat16 l0 = __float2bfloat16(v0 - __bfloat162float(h0));
    __nv_bfloat16 l1 = __float2bfloat16(v1 - __bfloat162float(h1));
    __nv_bfloat162 hp(h0, h1), lp(l0, l1);
    hi = *(uint32_t*)&hp; lo = *(uint32_t*)&lp;
}

// Merged weight split: blocks [0,512) -> WT1 rows; blocks [512,768) -> WT2 a/s.
__global__ void k_split_w(const float* __restrict__ W1a, const float* __restrict__ W1s,
                          const float* __restrict__ W2a, const float* __restrict__ W2s)
{
    int b = blockIdx.x;
    int k = threadIdx.x;   // 0..255
    if (b < 512) {
        if (k >= 128) return;
        const float* W = (b < 256) ? W1a : W1s;
        int col = b & 255;
        float v = W[k * 256 + col];
        __nv_bfloat16 hi = __float2bfloat16(v);
        __nv_bfloat16 lo = __float2bfloat16(v - __bfloat162float(hi));
        g_WT1[(size_t)b * 384 + k]       = hi;
        g_WT1[(size_t)b * 384 + 128 + k] = hi;
        g_WT1[(size_t)b * 384 + 256 + k] = lo;
    } else {
        int n = (b - 512) & 127;
        int which = (b - 512) >> 7;   // 0: W2a, 1: W2s
        const float* W = which ? W2s : W2a;
        __nv_bfloat16* dst = which ? g_WT2s : g_WT2a;
        float v = W[k * 128 + n];
        __nv_bfloat16 hi = __float2bfloat16(v);
        __nv_bfloat16 lo = __float2bfloat16(v - __bfloat162float(hi));
        dst[(size_t)n * 768 + k]       = hi;
        dst[(size_t)n * 768 + 256 + k] = hi;
        dst[(size_t)n * 768 + 512 + k] = lo;
    }
}

// ---------------- layer-1 aggregation of RAW features (4-way unrolled) ----------
__global__ void k_agg_h(const float4* __restrict__ h4) {
    int n = blockIdx.x;
    int t = threadIdx.x;   // 32 threads
    float di = g_dinv[n];
    float4 x = h4[(size_t)n * 32 + t];
    float w0 = di * di;
    float4 a0 = make_float4(x.x * w0, x.y * w0, x.z * w0, x.w * w0);
    float4 a1 = make_float4(0.f, 0.f, 0.f, 0.f);
    float4 a2 = make_float4(0.f, 0.f, 0.f, 0.f);
    float4 a3 = make_float4(0.f, 0.f, 0.f, 0.f);

    int e0 = g_rowptr[n], e1 = g_rowptr[n + 1];
    int e = e0;
    for (; e + 4 <= e1; e += 4) {
        int s0 = g_col[e], s1 = g_col[e + 1], s2 = g_col[e + 2], s3 = g_col[e + 3];
        float ws0 = g_dinv[s0] * di, ws1 = g_dinv[s1] * di;
        float ws2 = g_dinv[s2] * di, ws3 = g_dinv[s3] * di;
        float4 v0 = h4[(size_t)s0 * 32 + t];
        float4 v1 = h4[(size_t)s1 * 32 + t];
        float4 v2 = h4[(size_t)s2 * 32 + t];
        float4 v3 = h4[(size_t)s3 * 32 + t];
        a0.x += v0.x * ws0; a0.y += v0.y * ws0; a0.z += v0.z * ws0; a0.w += v0.w * ws0;
        a1.x += v1.x * ws1; a1.y += v1.y * ws1; a1.z += v1.z * ws1; a1.w += v1.w * ws1;
        a2.x += v2.x * ws2; a2.y += v2.y * ws2; a2.z += v2.z * ws2; a2.w += v2.w * ws2;
        a3.x += v3.x * ws3; a3.y += v3.y * ws3; a3.z += v3.z * ws3; a3.w += v3.w * ws3;
    }
    for (; e < e1; e++) {
        int s = g_col[e];
        float ws = g_dinv[s] * di;
        float4 v = h4[(size_t)s * 32 + t];
        a0.x += v.x * ws; a0.y += v.y * ws; a0.z += v.z * ws; a0.w += v.w * ws;
    }
    float4 acc = make_float4(a0.x + a1.x + a2.x + a3.x, a0.y + a1.y + a2.y + a3.y,
                             a0.z + a1.z + a2.z + a3.z, a0.w + a1.w + a2.w + a3.w);
    bf4 hv, lv; split4(acc, hv, lv);
    int c = t * 4;
    *(bf4*)&g_A1[(size_t)n * 384 + c]       = hv;
    *(bf4*)&g_A1[(size_t)n * 384 + 128 + c] = lv;
    *(bf4*)&g_A1[(size_t)n * 384 + 256 + c] = hv;
}

// ---------------- GCN aggregation layer 2 (4-way unrolled) ----------------------
__global__ void k_agg2(const float4* __restrict__ XW4,   // [NN][64] float4 (F2=256)
                       float* __restrict__ xout,          // [NN][128]
                       __nv_bfloat16* __restrict__ Hb,    // [NN][256] hi|lo
                       const float* __restrict__ b2a, const float* __restrict__ b2s)
{
    int n = blockIdx.x;
    int t = threadIdx.x;   // 64 threads
    float di = g_dinv[n];
    float4 x = XW4[(size_t)n * 64 + t];
    float w0 = di * di;
    float4 a0 = make_float4(x.x * w0, x.y * w0, x.z * w0, x.w * w0);
    float4 a1 = make_float4(0.f, 0.f, 0.f, 0.f);
    float4 a2 = make_float4(0.f, 0.f, 0.f, 0.f);
    float4 a3 = make_float4(0.f, 0.f, 0.f, 0.f);

    int e0 = g_rowptr[n], e1 = g_rowptr[n + 1];
    int e = e0;
    for (; e + 4 <= e1; e += 4) {
        int s0 = g_col[e], s1 = g_col[e + 1], s2 = g_col[e + 2], s3 = g_col[e + 3];
        float ws0 = g_dinv[s0] * di, ws1 = g_dinv[s1] * di;
        float ws2 = g_dinv[s2] * di, ws3 = g_dinv[s3] * di;
        float4 v0 = XW4[(size_t)s0 * 64 + t];
        float4 v1 = XW4[(size_t)s1 * 64 + t];
        float4 v2 = XW4[(size_t)s2 * 64 + t];
        float4 v3 = XW4[(size_t)s3 * 64 + t];
        a0.x += v0.x * ws0; a0.y += v0.y * ws0; a0.z += v0.z * ws0; a0.w += v0.w * ws0;
        a1.x += v1.x * ws1; a1.y += v1.y * ws1; a1.z += v1.z * ws1; a1.w += v1.w * ws1;
        a2.x += v2.x * ws2; a2.y += v2.y * ws2; a2.z += v2.z * ws2; a2.w += v2.w * ws2;
        a3.x += v3.x * ws3; a3.y += v3.y * ws3; a3.z += v3.z * ws3; a3.w += v3.w * ws3;
    }
    for (; e < e1; e++) {
        int s = g_col[e];
        float ws = g_dinv[s] * di;
        float4 v = XW4[(size_t)s * 64 + t];
        a0.x += v.x * ws; a0.y += v.y * ws; a0.z += v.z * ws; a0.w += v.w * ws;
    }
    float4 acc = make_float4(a0.x + a1.x + a2.x + a3.x, a0.y + a1.y + a2.y + a3.y,
                             a0.z + a1.z + a2.z + a3.z, a0.w + a1.w + a2.w + a3.w);

    int c = t * 4;
    if (c < 128) {
        float4 bv = *(const float4*)&b2a[c];
        acc.x += bv.x; acc.y += bv.y; acc.z += bv.z; acc.w += bv.w;
        *(float4*)&xout[(size_t)n * 128 + c] = acc;
    } else {
        int cc = c - 128;
        float4 bv = *(const float4*)&b2s[cc];
        acc.x += bv.x; acc.y += bv.y; acc.z += bv.z; acc.w += bv.w;
        bf4 hv, lv; split4(acc, hv, lv);
        *(bf4*)&Hb[(size_t)n * 256 + cc]       = hv;
        *(bf4*)&Hb[(size_t)n * 256 + 128 + cc] = lv;
    }
}

// ---------------- bf16 tensor-core GEMM: C[M,N] = A[M,K] @ B[N,K]^T ----------------
// (proven shape: 128x128 tile, BK=32, 3-stage, 2 CTA/SM)
#define BK 32
#define SP 40
#define STG_ELE (128 * SP)
#define GEMM_SMEM (3 * 2 * STG_ELE * 2)   // 61440 bytes

template <int MODE>
__global__ void __launch_bounds__(256, 2)
gemm_bf(const __nv_bfloat16* __restrict__ A, const __nv_bfloat16* __restrict__ B,
        const __nv_bfloat16* __restrict__ A2, const __nv_bfloat16* __restrict__ B2,
        int K, float* __restrict__ C, int ldc, int M,
        const float* __restrict__ bias_a, const float* __restrict__ bias_s)
{
    extern __shared__ __align__(16) __nv_bfloat16 smem[];
    __nv_bfloat16* As = smem;
    __nv_bfloat16* Bs = smem + 3 * STG_ELE;

    const int tid  = threadIdx.x;
    const int m0   = blockIdx.y * 128;
    const __nv_bfloat16* Ap = A;
    const __nv_bfloat16* Bp = B;
    int n0, coff;
    if (MODE == 0) {
        if (blockIdx.x) { Ap = A2; Bp = B2; }
        n0 = 0; coff = blockIdx.x * 128;
    } else {
        n0 = blockIdx.x * 128; coff = 0;
    }
    const int w    = tid >> 5;
    const int lane = tid & 31;
    const int wm   = w >> 2;
    const int wn   = w & 3;
    const int nch  = K / BK;

    float acc[4][4][4];
    #pragma unroll
    for (int mt = 0; mt < 4; mt++)
        #pragma unroll
        for (int nt = 0; nt < 4; nt++)
            #pragma unroll
            for (int i = 0; i < 4; i++) acc[mt][nt][i] = 0.0f;

    auto load_stage = [&](int kc, int st) {
        #pragma unroll
        for (int i = 0; i < 2; i++) {
            int c = tid + i * 256;
            int r = c >> 2, q = c & 3;
            {
                int grow = m0 + r;
                int rg = grow < M ? grow : M - 1;
                const __nv_bfloat16* src = Ap + (size_t)rg * K + kc * BK + q * 8;
                uint32_t dst = (uint32_t)__cvta_generic_to_shared(&As[st * STG_ELE + r * SP + q * 8]);
                asm volatile("cp.async.cg.shared.global [%0], [%1], 16;\n"
                             :: "r"(dst), "l"(src));
            }
            {
                const __nv_bfloat16* src = Bp + (size_t)(n0 + r) * K + kc * BK + q * 8;
                uint32_t dst = (uint32_t)__cvta_generic_to_shared(&Bs[st * STG_ELE + r * SP + q * 8]);
                asm volatile("cp.async.cg.shared.global [%0], [%1], 16;\n"
                             :: "r"(dst), "l"(src));
            }
        }
    };

    auto compute = [&](int st) {
        #pragma unroll
        for (int ks = 0; ks < 2; ks++) {
            uint32_t a[4][4];
            #pragma unroll
            for (int mt = 0; mt < 4; mt++) {
                int row = wm * 64 + mt * 16 + (lane & 15);
                int col = ks * 16 + ((lane >> 4) << 3);
                uint32_t ad = (uint32_t)__cvta_generic_to_shared(&As[st * STG_ELE + row * SP + col]);
                asm volatile("ldmatrix.sync.aligned.m8n8.x4.shared.b16 {%0,%1,%2,%3}, [%4];"
                             : "=r"(a[mt][0]), "=r"(a[mt][1]), "=r"(a[mt][2]), "=r"(a[mt][3])
                             : "r"(ad));
            }
            uint32_t b[2][4];
            #pragma unroll
            for (int p = 0; p < 2; p++) {
                int j = lane >> 3, l = lane & 7;
                int row = wn * 32 + p * 16 + ((j >> 1) << 3) + l;
                int col = ks * 16 + ((j & 1) << 3);
                uint32_t bd = (uint32_t)__cvta_generic_to_shared(&Bs[st * STG_ELE + row * SP + col]);
                asm volatile("ldmatrix.sync.aligned.m8n8.x4.shared.b16 {%0,%1,%2,%3}, [%4];"
                             : "=r"(b[p][0]), "=r"(b[p][1]), "=r"(b[p][2]), "=r"(b[p][3])
                             : "r"(bd));
            }
            #pragma unroll
            for (int mt = 0; mt < 4; mt++)
                #pragma unroll
                for (int nt = 0; nt < 4; nt++) {
                    uint32_t b0 = b[nt >> 1][(nt & 1) * 2];
                    uint32_t b1 = b[nt >> 1][(nt & 1) * 2 + 1];
                    asm volatile(
                        "mma.sync.aligned.m16n8k16.row.col.f32.bf16.bf16.f32 "
                        "{%0,%1,%2,%3}, {%4,%5,%6,%7}, {%8,%9}, {%0,%1,%2,%3};"
                        : "+f"(acc[mt][nt][0]), "+f"(acc[mt][nt][1]),
                          "+f"(acc[mt][nt][2]), "+f"(acc[mt][nt][3])
                        : "r"(a[mt][0]), "r"(a[mt][1]), "r"(a[mt][2]), "r"(a[mt][3]),
                          "r"(b0), "r"(b1));
                }
        }
    };

    load_stage(0, 0);
    asm volatile("cp.async.commit_group;");
    load_stage(1, 1);
    asm volatile("cp.async.commit_group;");

    #pragma unroll 1
    for (int kc = 0; kc < nch; kc++) {
        asm volatile("cp.async.wait_group 1;");
        __syncthreads();
        if (kc + 2 < nch) {
            load_stage(kc + 2, (kc + 2) % 3);
            asm volatile("cp.async.commit_group;");
        } else {
            asm volatile("cp.async.commit_group;");
        }
        compute(kc % 3);
    }

    #pragma unroll
    for (int mt = 0; mt < 4; mt++)
        #pragma unroll
        for (int nt = 0; nt < 4; nt++) {
            int row = m0 + wm * 64 + mt * 16 + (lane >> 2);
            int col = n0 + wn * 32 + nt * 8 + (lane & 3) * 2;
            if (MODE == 0) {
                if (row < M)
                    *(float2*)&C[(size_t)row * ldc + coff + col] =
                        make_float2(acc[mt][nt][0], acc[mt][nt][1]);
                if (row + 8 < M)
                    *(float2*)&C[(size_t)(row + 8) * ldc + coff + col] =
                        make_float2(acc[mt][nt][2], acc[mt][nt][3]);
            } else {
                const float* bias = (col < 256) ? bias_a : bias_s;
                __nv_bfloat16* dst = (col < 256) ? g_A2a : g_A2s;
                int lc = col & 255;
                float bv0 = bias[lc], bv1 = bias[lc + 1];
                #pragma unroll
                for (int half = 0; half < 2; half++) {
                    int r = row + half * 8;
                    if (r < M) {
                        float v0 = fmaxf(acc[mt][nt][half * 2]     + bv0, 0.f);
                        float v1 = fmaxf(acc[mt][nt][half * 2 + 1] + bv1, 0.f);
                        uint32_t hi, lo; split2(v0, v1, hi, lo);
                        *(uint32_t*)&dst[(size_t)r * 768 + lc]       = hi;
                        *(uint32_t*)&dst[(size_t)r * 768 + 256 + lc] = lo;
                        *(uint32_t*)&dst[(size_t)r * 768 + 512 + lc] = hi;
                    }
                }
            }
        }
}

// ---------------- Gram via bf16 tensor cores (mma.sync), SYMMETRIC -----------------
// 128x128 tiles, BK=64, 2-stage pipeline (proven round-11 shape), 2 CTA/SM.
// All s_ stores use st.global.cs (write-once output; keep L2 for Hb/CSR).
#define NT 79
#define NTILES (NT * (NT + 1) / 2)  // 3160
#define GBK 64
#define GSP 72                      // pitch: 64 bf16 + 8 pad (144B rows)
#define G_STG (128 * GSP)
#define GRAM_SMEM (2 * 2 * G_STG * 2)   // 73728 bytes
#define TP 66                       // transpose staging pitch (floats)

__global__ void __launch_bounds__(256, 2)
gram_mma(const __nv_bfloat16* __restrict__ Hb, float* __restrict__ C)
{
    extern __shared__ __align__(16) __nv_bfloat16 smem[];
    __nv_bfloat16* As = smem;                 // [2][G_STG]
    __nv_bfloat16* Bs = smem + 2 * G_STG;     // [2][G_STG]
    float* sT = (float*)smem;                 // reused after mainloop: [128][TP]

    // ---- map linear tile id -> (ti, tj) with ti <= tj ----
    int t = blockIdx.x;
    int ti = (int)((2.0f * NT + 1.0f -
                    sqrtf((2.0f * NT + 1.0f) * (2.0f * NT + 1.0f) - 8.0f * (float)t)) * 0.5f);
    if (ti < 0) ti = 0;
    if (ti > NT - 1) ti = NT - 1;
    #pragma unroll 1
    while (ti > 0 && (ti * NT - ti * (ti - 1) / 2) > t) ti--;
    #pragma unroll 1
    while (ti < NT - 1 && ((ti + 1) * NT - (ti + 1) * ti / 2) <= t) ti++;
    const int tj = ti + (t - (ti * NT - ti * (ti - 1) / 2));

    const int m0 = ti * 128;
    const int n0 = tj * 128;

    const int tid  = threadIdx.x;
    const int w    = tid >> 5;
    const int lane = tid & 31;
    const int wm   = w >> 2;
    const int wn   = w & 3;

    float acc[4][4][4];
    #pragma unroll
    for (int mt = 0; mt < 4; mt++)
        #pragma unroll
        for (int nt = 0; nt < 4; nt++)
            #pragma unroll
            for (int i = 0; i < 4; i++) acc[mt][nt][i] = 0.0f;

    // load one BK=64 chunk: A/B each 128 rows x 8 16B-chunks = 1024 cp.async
    auto load_stage = [&](int kc, int st) {
        #pragma unroll
        for (int i = 0; i < 4; i++) {
            int c = tid + i * 256;            // 0..1023
            int r = c >> 3, q = c & 7;
            {
                int grow = m0 + r;
                int rg = grow < NN ? grow : NN - 1;
                const __nv_bfloat16* src = Hb + (size_t)rg * 256 + kc * GBK + q * 8;
                uint32_t dst = (uint32_t)__cvta_generic_to_shared(&As[st * G_STG + r * GSP + q * 8]);
                asm volatile("cp.async.cg.shared.global [%0], [%1], 16;\n"
                             :: "r"(dst), "l"(src));
            }
            {
                int grow = n0 + r;
                int rg = grow < NN ? grow : NN - 1;
                const __nv_bfloat16* src = Hb + (size_t)rg * 256 + kc * GBK + q * 8;
                uint32_t dst = (uint32_t)__cvta_generic_to_shared(&Bs[st * G_STG + r * GSP + q * 8]);
                asm volatile("cp.async.cg.shared.global [%0], [%1], 16;\n"
                             :: "r"(dst), "l"(src));
            }
        }
    };

    auto compute = [&](int st) {
        #pragma unroll
        for (int ks = 0; ks < 4; ks++) {
            uint32_t a[4][4];
            #pragma unroll
            for (int mt = 0; mt < 4; mt++) {
                int row = wm * 64 + mt * 16 + (lane & 15);
                int col = ks * 16 + ((lane >> 4) << 3);
                uint32_t ad = (uint32_t)__cvta_generic_to_shared(&As[st * G_STG + row * GSP + col]);
                asm volatile("ldmatrix.sync.aligned.m8n8.x4.shared.b16 {%0,%1,%2,%3}, [%4];"
                             : "=r"(a[mt][0]), "=r"(a[mt][1]), "=r"(a[mt][2]), "=r"(a[mt][3])
                             : "r"(ad));
            }
            uint32_t b[2][4];
            #pragma unroll
            for (int p = 0; p < 2; p++) {
                int j = lane >> 3, l = lane & 7;
                int row = wn * 32 + p * 16 + ((j >> 1) << 3) + l;
                int col = ks * 16 + ((j & 1) << 3);
                uint32_t bd = (uint32_t)__cvta_generic_to_shared(&Bs[st * G_STG + row * GSP + col]);
                asm volatile("ldmatrix.sync.aligned.m8n8.x4.shared.b16 {%0,%1,%2,%3}, [%4];"
                             : "=r"(b[p][0]), "=r"(b[p][1]), "=r"(b[p][2]), "=r"(b[p][3])
                             : "r"(bd));
            }
            #pragma unroll
            for (int mt = 0; mt < 4; mt++)
                #pragma unroll
                for (int nt = 0; nt < 4; nt++) {
                    uint32_t b0 = b[nt >> 1][(nt & 1) * 2];
                    uint32_t b1 = b[nt >> 1][(nt & 1) * 2 + 1];
                    asm volatile(
                        "mma.sync.aligned.m16n8k16.row.col.f32.bf16.bf16.f32 "
                        "{%0,%1,%2,%3}, {%4,%5,%6,%7}, {%8,%9}, {%0,%1,%2,%3};"
                        : "+f"(acc[mt][nt][0]), "+f"(acc[mt][nt][1]),
                          "+f"(acc[mt][nt][2]), "+f"(acc[mt][nt][3])
                        : "r"(a[mt][0]), "r"(a[mt][1]), "r"(a[mt][2]), "r"(a[mt][3]),
                          "r"(b0), "r"(b1));
                }
        }
    };

    // double-buffered mainloop over 4 chunks
    load_stage(0, 0);
    asm volatile("cp.async.commit_group;");

    #pragma unroll 1
    for (int kc = 0; kc < 4; kc++) {
        if (kc + 1 < 4) {
            load_stage(kc + 1, (kc + 1) & 1);
            asm volatile("cp.async.commit_group;");
            asm volatile("cp.async.wait_group 1;");
        } else {
            asm volatile("cp.async.wait_group 0;");
        }
        __syncthreads();
        compute(kc & 1);
        __syncthreads();
    }

    // ---- direct write (streaming): C[m0 + rows, n0 + cols] ----
    #pragma unroll
    for (int mt = 0; mt < 4; mt++)
        #pragma unroll
        for (int nt = 0; nt < 4; nt++) {
            int row = m0 + wm * 64 + mt * 16 + (lane >> 2);
            int col = n0 + wn * 32 + nt * 8 + (lane & 3) * 2;
            if (col < NN) {
                if (row < NN)
                    stcs2(&C[(size_t)row * NN + col], acc[mt][nt][0], acc[mt][nt][1]);
                if (row + 8 < NN)
                    stcs2(&C[(size_t)(row + 8) * NN + col], acc[mt][nt][2], acc[mt][nt][3]);
            }
        }

    // ---- transposed write for off-diagonal tiles (streaming) ----
    if (ti != tj) {
        #pragma unroll
        for (int h = 0; h < 2; h++) {
            __syncthreads();
            if (wm == h) {
                #pragma unroll
                for (int mt = 0; mt < 4; mt++) {
                    int rloc = mt * 16 + (lane >> 2);
                    #pragma unroll
                    for (int nt = 0; nt < 4; nt++) {
                        int cloc = wn * 32 + nt * 8 + (lane & 3) * 2;
                        sT[(cloc)     * TP + rloc]     = acc[mt][nt][0];
                        sT[(cloc + 1) * TP + rloc]     = acc[mt][nt][1];
                        sT[(cloc)     * TP + rloc + 8] = acc[mt][nt][2];
                        sT[(cloc + 1) * TP + rloc + 8] = acc[mt][nt][3];
                    }
                }
            }
            __syncthreads();
            #pragma unroll
            for (int e = 0; e < 8; e++) {
                int idx = tid + 256 * e;
                int cc  = idx >> 4;
                int rr  = (idx & 15) * 4;
                int grow = n0 + cc;
                int gcol = m0 + h * 64 + rr;
                if (grow < NN) {
                    float4 v = make_float4(sT[cc * TP + rr],
                                           sT[cc * TP + rr + 1],
                                           sT[cc * TP + rr + 2],
                                           sT[cc * TP + rr + 3]);
                    if (gcol + 3 < NN) {
                        stcs4(&C[(size_t)grow * NN + gcol], v);
                    } else {
                        float vv[4] = {v.x, v.y, v.z, v.w};
                        #pragma unroll
                        for (int k = 0; k < 4; k++)
                            if (gcol + k < NN) stcs1(&C[(size_t)grow * NN + gcol + k], vv[k]);
                    }
                }
            }
        }
    }
}

// ---------------- launcher ----------------
extern "C" void kernel_launch(void* const* d_in, const int* in_sizes, int n_in,
                              void* d_out, int out_size)
{
    const float* h   = (const float*)d_in[0];
    const float* W1a = (const float*)d_in[1];
    const float* b1a = (const float*)d_in[2];
    const float* W2a = (const float*)d_in[3];
    const float* b2a = (const float*)d_in[4];
    const float* W1s = (const float*)d_in[5];
    const float* b1s = (const float*)d_in[6];
    const float* W2s = (const float*)d_in[7];
    const float* b2s = (const float*)d_in[8];
    const int*   ei  = (const int*)d_in[9];
    const int* src = ei;
    const int* dst = ei + NE;
    float* out = (float*)d_out;

    float* pXW2;
    __nv_bfloat16 *pHb, *pA1, *pA2a, *pA2s, *pWT1, *pWT2a, *pWT2s;
    int* pCnt;
    cudaGetSymbolAddress((void**)&pXW2,  g_XW2);
    cudaGetSymbolAddress((void**)&pHb,   g_Hb);
    cudaGetSymbolAddress((void**)&pA1,   g_A1);
    cudaGetSymbolAddress((void**)&pA2a,  g_A2a);
    cudaGetSymbolAddress((void**)&pA2s,  g_A2s);
    cudaGetSymbolAddress((void**)&pWT1,  g_WT1);
    cudaGetSymbolAddress((void**)&pWT2a, g_WT2a);
    cudaGetSymbolAddress((void**)&pWT2s, g_WT2s);
    cudaGetSymbolAddress((void**)&pCnt,  g_cnt);

    cudaFuncSetAttribute(gram_mma,   cudaFuncAttributeMaxDynamicSharedMemorySize, GRAM_SMEM);
    cudaFuncSetAttribute(gemm_bf<0>, cudaFuncAttributeMaxDynamicSharedMemorySize, GEMM_SMEM);
    cudaFuncSetAttribute(gemm_bf<1>, cudaFuncAttributeMaxDynamicSharedMemorySize, GEMM_SMEM);

    // graph prep + weight conversion
    cudaMemsetAsync(pCnt, 0, NN * sizeof(int));
    k_count<<<(NE + 255) / 256, 256>>>(dst);
    k_scan <<<1, 1024>>>();
    k_fill <<<(NE + 255) / 256, 256>>>(src, dst);
    k_split_w<<<768, 256>>>(W1a, W1s, W2a, W2s);

    // layer 1 (aggregate-first): hagg = A_norm@h -> A1; H1 = relu(hagg@W1+b) -> A2a/A2s
    k_agg_h<<<NN, 32>>>((const float4*)h);
    gemm_bf<1><<<dim3(4, NT), 256, GEMM_SMEM>>>(pA1, pWT1, nullptr, nullptr, 384,
                                                nullptr, 0, NN, b1a, b1s);

    // layer 2 (transform-first), both branches in ONE launch
    gemm_bf<0><<<dim3(2, NT), 256, GEMM_SMEM>>>(pA2a, pWT2a, pA2s, pWT2s, 768,
                                                pXW2, 256, NN, nullptr, nullptr);
    k_agg2<<<NN, 64>>>((const float4*)pXW2, out, pHb, b2a, b2s);

    // s_ = h_ @ h_^T: symmetric 128x128 tiles, BK=64, double-buffered, streaming stores
    gram_mma<<<NTILES, 256, GRAM_SMEM>>>(pHb, out + S_OFF);

    // h passthrough
    cudaMemcpyAsync(out + H_OFF, h, (size_t)NN * 128 * sizeof(float),
                    cudaMemcpyDeviceToDevice);
}

// round 14
// speedup vs baseline: 1.0020x; 1.0020x over previous
#include <cuda_runtime.h>
#include <cuda_bf16.h>
#include <cstdint>

// Problem constants
#define NN   10000
#define NE   320000
#define F2   256     // 2*OUT

// Output layout: x_ [NN*128], s_ [NN*NN], h [NN*128]
#define S_OFF  (NN * 128)
#define H_OFF  (S_OFF + (size_t)NN * NN)

// ---------------- static device scratch (no allocs allowed) ----------------
__device__ float g_XW2[NN * F2];              // H1 @ [W2a | W2s] (fp32, gathered by agg2)
__device__ __nv_bfloat16 g_A1 [NN * 384];     // agg(h) split: [hi | lo | hi]    (K=384)
__device__ __nv_bfloat16 g_A2a[NN * 768];     // H1a split: [hi | lo | hi]       (K=768)
__device__ __nv_bfloat16 g_A2s[NN * 768];     // H1s split
__device__ __nv_bfloat16 g_WT1 [512 * 384];   // [W1a|W1s]^T split: [whi | whi | wlo]
__device__ __nv_bfloat16 g_WT2a[128 * 768];   // W2a^T split
__device__ __nv_bfloat16 g_WT2s[128 * 768];   // W2s^T split
__device__ __nv_bfloat16 g_Hb[NN * 256];      // h_ split: cols [0,128)=hi, [128,256)=lo
__device__ float g_dinv[NN];
__device__ int   g_cnt[NN];
__device__ int   g_cur[NN];
__device__ int   g_rowptr[NN + 1];
__device__ int   g_col[NE];

// ---------------- graph preprocessing ----------------
__global__ void k_count(const int* __restrict__ dst) {
    int e = blockIdx.x * 256 + threadIdx.x;
    if (e < NE) atomicAdd(&g_cnt[dst[e]], 1);
}

// scan cnt -> rowptr (also seeds g_cur = rowptr), AND compute dinv (fused)
__global__ void k_scan() {
    __shared__ int s[1024];
    int t = threadIdx.x;
    const int CH = 10;
    int base = t * CH;
    int sum = 0;
    #pragma unroll
    for (int i = 0; i < CH; i++) { int idx = base + i; if (idx < NN) sum += g_cnt[idx]; }
    s[t] = sum;
    __syncthreads();
    for (int off = 1; off < 1024; off <<= 1) {
        int v = (t >= off) ? s[t - off] : 0;
        __syncthreads();
        s[t] += v;
        __syncthreads();
    }
    int run = (t > 0) ? s[t - 1] : 0;
    #pragma unroll
    for (int i = 0; i < CH; i++) {
        int idx = base + i;
        if (idx < NN) {
            g_rowptr[idx] = run;
            g_cur[idx]    = run;
            int c = g_cnt[idx];
            run += c;
            g_dinv[idx] = rsqrtf(1.0f + (float)c);
        }
    }
    if (t == 1023) g_rowptr[NN] = s[1023];
}

__global__ void k_fill(const int* __restrict__ src, const int* __restrict__ dst) {
    int e = blockIdx.x * 256 + threadIdx.x;
    if (e < NE) {
        int d = dst[e];
        int pos = atomicAdd(&g_cur[d], 1);
        g_col[pos] = src[e];
    }
}

// ---------------- split helpers ----------------
struct alignas(8) bf4 { __nv_bfloat162 a, b; };

__device__ __forceinline__ void split4(float4 v, bf4& hv, bf4& lv) {
    __nv_bfloat16 h0 = __float2bfloat16(v.x), h1 = __float2bfloat16(v.y);
    __nv_bfloat16 h2 = __float2bfloat16(v.z), h3 = __float2bfloat16(v.w);
    __nv_bfloat16 l0 = __float2bfloat16(v.x - __bfloat162float(h0));
    __nv_bfloat16 l1 = __float2bfloat16(v.y - __bfloat162float(h1));
    __nv_bfloat16 l2 = __float2bfloat16(v.z - __bfloat162float(h2));
    __nv_bfloat16 l3 = __float2bfloat16(v.w - __bfloat162float(h3));
    hv.a = __nv_bfloat162(h0, h1); hv.b = __nv_bfloat162(h2, h3);
    lv.a = __nv_bfloat162(l0, l1); lv.b = __nv_bfloat162(l2, l3);
}

__device__ __forceinline__ void split2(float v0, float v1, uint32_t& hi, uint32_t& lo) {
    __nv_bfloat16 h0 = __float2bfloat16(v0), h1 = __float2bfloat16(v1);
    __nv_bfloat16 l0 = __float2bfloat16(v0 - __bfloat162float(h0));
    __nv_bfloat16 l1 = __float2bfloat16(v1 - __bfloat162float(h1));
    __nv_bfloat162 hp(h0, h1), lp(l0, l1);
    hi = *(uint32_t*)&hp; lo = *(uint32_t*)&lp;
}

// Merged weight split: blocks [0,512) -> WT1 rows; blocks [512,768) -> WT2 a/s.
__global__ void k_split_w(const float* __restrict__ W1a, const float* __restrict__ W1s,
                          const float* __restrict__ W2a, const float* __restrict__ W2s)
{
    int b = blockIdx.x;
    int k = threadIdx.x;   // 0..255
    if (b < 512) {
        if (k >= 128) return;
        const float* W = (b < 256) ? W1a : W1s;
        int col = b & 255;
        float v = W[k * 256 + col];
        __nv_bfloat16 hi = __float2bfloat16(v);
        __nv_bfloat16 lo = __float2bfloat16(v - __bfloat162float(hi));
        g_WT1[(size_t)b * 384 + k]       = hi;
        g_WT1[(size_t)b * 384 + 128 + k] = hi;
        g_WT1[(size_t)b * 384 + 256 + k] = lo;
    } else {
        int n = (b - 512) & 127;
        int which = (b - 512) >> 7;   // 0: W2a, 1: W2s
        const float* W = which ? W2s : W2a;
        __nv_bfloat16* dst = which ? g_WT2s : g_WT2a;
        float v = W[k * 128 + n];
        __nv_bfloat16 hi = __float2bfloat16(v);
        __nv_bfloat16 lo = __float2bfloat16(v - __bfloat162float(hi));
        dst[(size_t)n * 768 + k]       = hi;
        dst[(size_t)n * 768 + 256 + k] = hi;
        dst[(size_t)n * 768 + 512 + k] = lo;
    }
}

// ---------------- layer-1 aggregation of RAW features (4-way unrolled) ----------
__global__ void k_agg_h(const float4* __restrict__ h4) {
    int n = blockIdx.x;
    int t = threadIdx.x;   // 32 threads
    float di = g_dinv[n];
    float4 x = h4[(size_t)n * 32 + t];
    float w0 = di * di;
    float4 a0 = make_float4(x.x * w0, x.y * w0, x.z * w0, x.w * w0);
    float4 a1 = make_float4(0.f, 0.f, 0.f, 0.f);
    float4 a2 = make_float4(0.f, 0.f, 0.f, 0.f);
    float4 a3 = make_float4(0.f, 0.f, 0.f, 0.f);

    int e0 = g_rowptr[n], e1 = g_rowptr[n + 1];
    int e = e0;
    for (; e + 4 <= e1; e += 4) {
        int s0 = g_col[e], s1 = g_col[e + 1], s2 = g_col[e + 2], s3 = g_col[e + 3];
        float ws0 = g_dinv[s0] * di, ws1 = g_dinv[s1] * di;
        float ws2 = g_dinv[s2] * di, ws3 = g_dinv[s3] * di;
        float4 v0 = h4[(size_t)s0 * 32 + t];
        float4 v1 = h4[(size_t)s1 * 32 + t];
        float4 v2 = h4[(size_t)s2 * 32 + t];
        float4 v3 = h4[(size_t)s3 * 32 + t];
        a0.x += v0.x * ws0; a0.y += v0.y * ws0; a0.z += v0.z * ws0; a0.w += v0.w * ws0;
        a1.x += v1.x * ws1; a1.y += v1.y * ws1; a1.z += v1.z * ws1; a1.w += v1.w * ws1;
        a2.x += v2.x * ws2; a2.y += v2.y * ws2; a2.z += v2.z * ws2; a2.w += v2.w * ws2;
        a3.x += v3.x * ws3; a3.y += v3.y * ws3; a3.z += v3.z * ws3; a3.w += v3.w * ws3;
    }
    for (; e < e1; e++) {
        int s = g_col[e];
        float ws = g_dinv[s] * di;
        float4 v = h4[(size_t)s * 32 + t];
        a0.x += v.x * ws; a0.y += v.y * ws; a0.z += v.z * ws; a0.w += v.w * ws;
    }
    float4 acc = make_float4(a0.x + a1.x + a2.x + a3.x, a0.y + a1.y + a2.y + a3.y,
                             a0.z + a1.z + a2.z + a3.z, a0.w + a1.w + a2.w + a3.w);
    bf4 hv, lv; split4(acc, hv, lv);
    int c = t * 4;
    *(bf4*)&g_A1[(size_t)n * 384 + c]       = hv;
    *(bf4*)&g_A1[(size_t)n * 384 + 128 + c] = lv;
    *(bf4*)&g_A1[(size_t)n * 384 + 256 + c] = hv;
}

// ---------------- GCN aggregation layer 2 (4-way unrolled) ----------------------
__global__ void k_agg2(const float4* __restrict__ XW4,   // [NN][64] float4 (F2=256)
                       float* __restrict__ xout,          // [NN][128]
                       __nv_bfloat16* __restrict__ Hb,    // [NN][256] hi|lo
                       const float* __restrict__ b2a, const float* __restrict__ b2s)
{
    int n = blockIdx.x;
    int t = threadIdx.x;   // 64 threads
    float di = g_dinv[n];
    float4 x = XW4[(size_t)n * 64 + t];
    float w0 = di * di;
    float4 a0 = make_float4(x.x * w0, x.y * w0, x.z * w0, x.w * w0);
    float4 a1 = make_float4(0.f, 0.f, 0.f, 0.f);
    float4 a2 = make_float4(0.f, 0.f, 0.f, 0.f);
    float4 a3 = make_float4(0.f, 0.f, 0.f, 0.f);

    int e0 = g_rowptr[n], e1 = g_rowptr[n + 1];
    int e = e0;
    for (; e + 4 <= e1; e += 4) {
        int s0 = g_col[e], s1 = g_col[e + 1], s2 = g_col[e + 2], s3 = g_col[e + 3];
        float ws0 = g_dinv[s0] * di, ws1 = g_dinv[s1] * di;
        float ws2 = g_dinv[s2] * di, ws3 = g_dinv[s3] * di;
        float4 v0 = XW4[(size_t)s0 * 64 + t];
        float4 v1 = XW4[(size_t)s1 * 64 + t];
        float4 v2 = XW4[(size_t)s2 * 64 + t];
        float4 v3 = XW4[(size_t)s3 * 64 + t];
        a0.x += v0.x * ws0; a0.y += v0.y * ws0; a0.z += v0.z * ws0; a0.w += v0.w * ws0;
        a1.x += v1.x * ws1; a1.y += v1.y * ws1; a1.z += v1.z * ws1; a1.w += v1.w * ws1;
        a2.x += v2.x * ws2; a2.y += v2.y * ws2; a2.z += v2.z * ws2; a2.w += v2.w * ws2;
        a3.x += v3.x * ws3; a3.y += v3.y * ws3; a3.z += v3.z * ws3; a3.w += v3.w * ws3;
    }
    for (; e < e1; e++) {
        int s = g_col[e];
        float ws = g_dinv[s] * di;
        float4 v = XW4[(size_t)s * 64 + t];
        a0.x += v.x * ws; a0.y += v.y * ws; a0.z += v.z * ws; a0.w += v.w * ws;
    }
    float4 acc = make_float4(a0.x + a1.x + a2.x + a3.x, a0.y + a1.y + a2.y + a3.y,
                             a0.z + a1.z + a2.z + a3.z, a0.w + a1.w + a2.w + a3.w);

    int c = t * 4;
    if (c < 128) {
        float4 bv = *(const float4*)&b2a[c];
        acc.x += bv.x; acc.y += bv.y; acc.z += bv.z; acc.w += bv.w;
        *(float4*)&xout[(size_t)n * 128 + c] = acc;
    } else {
        int cc = c - 128;
        float4 bv = *(const float4*)&b2s[cc];
        acc.x += bv.x; acc.y += bv.y; acc.z += bv.z; acc.w += bv.w;
        bf4 hv, lv; split4(acc, hv, lv);
        *(bf4*)&Hb[(size_t)n * 256 + cc]       = hv;
        *(bf4*)&Hb[(size_t)n * 256 + 128 + cc] = lv;
    }
}

// ---------------- bf16 tensor-core GEMM: C[M,N] = A[M,K] @ B[N,K]^T ----------------
// (proven shape: 128x128 tile, BK=32, 3-stage, 2 CTA/SM)
#define BK 32
#define SP 40
#define STG_ELE (128 * SP)
#define GEMM_SMEM (3 * 2 * STG_ELE * 2)   // 61440 bytes

template <int MODE>
__global__ void __launch_bounds__(256, 2)
gemm_bf(const __nv_bfloat16* __restrict__ A, const __nv_bfloat16* __restrict__ B,
        const __nv_bfloat16* __restrict__ A2, const __nv_bfloat16* __restrict__ B2,
        int K, float* __restrict__ C, int ldc, int M,
        const float* __restrict__ bias_a, const float* __restrict__ bias_s)
{
    extern __shared__ __align__(16) __nv_bfloat16 smem[];
    __nv_bfloat16* As = smem;
    __nv_bfloat16* Bs = smem + 3 * STG_ELE;

    const int tid  = threadIdx.x;
    const int m0   = blockIdx.y * 128;
    const __nv_bfloat16* Ap = A;
    const __nv_bfloat16* Bp = B;
    int n0, coff;
    if (MODE == 0) {
        if (blockIdx.x) { Ap = A2; Bp = B2; }
        n0 = 0; coff = blockIdx.x * 128;
    } else {
        n0 = blockIdx.x * 128; coff = 0;
    }
    const int w    = tid >> 5;
    const int lane = tid & 31;
    const int wm   = w >> 2;
    const int wn   = w & 3;
    const int nch  = K / BK;

    float acc[4][4][4];
    #pragma unroll
    for (int mt = 0; mt < 4; mt++)
        #pragma unroll
        for (int nt = 0; nt < 4; nt++)
            #pragma unroll
            for (int i = 0; i < 4; i++) acc[mt][nt][i] = 0.0f;

    auto load_stage = [&](int kc, int st) {
        #pragma unroll
        for (int i = 0; i < 2; i++) {
            int c = tid + i * 256;
            int r = c >> 2, q = c & 3;
            {
                int grow = m0 + r;
                int rg = grow < M ? grow : M - 1;
                const __nv_bfloat16* src = Ap + (size_t)rg * K + kc * BK + q * 8;
                uint32_t dst = (uint32_t)__cvta_generic_to_shared(&As[st * STG_ELE + r * SP + q * 8]);
                asm volatile("cp.async.cg.shared.global [%0], [%1], 16;\n"
                             :: "r"(dst), "l"(src));
            }
            {
                const __nv_bfloat16* src = Bp + (size_t)(n0 + r) * K + kc * BK + q * 8;
                uint32_t dst = (uint32_t)__cvta_generic_to_shared(&Bs[st * STG_ELE + r * SP + q * 8]);
                asm volatile("cp.async.cg.shared.global [%0], [%1], 16;\n"
                             :: "r"(dst), "l"(src));
            }
        }
    };

    auto compute = [&](int st) {
        #pragma unroll
        for (int ks = 0; ks < 2; ks++) {
            uint32_t a[4][4];
            #pragma unroll
            for (int mt = 0; mt < 4; mt++) {
                int row = wm * 64 + mt * 16 + (lane & 15);
                int col = ks * 16 + ((lane >> 4) << 3);
                uint32_t ad = (uint32_t)__cvta_generic_to_shared(&As[st * STG_ELE + row * SP + col]);
                asm volatile("ldmatrix.sync.aligned.m8n8.x4.shared.b16 {%0,%1,%2,%3}, [%4];"
                             : "=r"(a[mt][0]), "=r"(a[mt][1]), "=r"(a[mt][2]), "=r"(a[mt][3])
                             : "r"(ad));
            }
            uint32_t b[2][4];
            #pragma unroll
            for (int p = 0; p < 2; p++) {
                int j = lane >> 3, l = lane & 7;
                int row = wn * 32 + p * 16 + ((j >> 1) << 3) + l;
                int col = ks * 16 + ((j & 1) << 3);
                uint32_t bd = (uint32_t)__cvta_generic_to_shared(&Bs[st * STG_ELE + row * SP + col]);
                asm volatile("ldmatrix.sync.aligned.m8n8.x4.shared.b16 {%0,%1,%2,%3}, [%4];"
                             : "=r"(b[p][0]), "=r"(b[p][1]), "=r"(b[p][2]), "=r"(b[p][3])
                             : "r"(bd));
            }
            #pragma unroll
            for (int mt = 0; mt < 4; mt++)
                #pragma unroll
                for (int nt = 0; nt < 4; nt++) {
                    uint32_t b0 = b[nt >> 1][(nt & 1) * 2];
                    uint32_t b1 = b[nt >> 1][(nt & 1) * 2 + 1];
                    asm volatile(
                        "mma.sync.aligned.m16n8k16.row.col.f32.bf16.bf16.f32 "
                        "{%0,%1,%2,%3}, {%4,%5,%6,%7}, {%8,%9}, {%0,%1,%2,%3};"
                        : "+f"(acc[mt][nt][0]), "+f"(acc[mt][nt][1]),
                          "+f"(acc[mt][nt][2]), "+f"(acc[mt][nt][3])
                        : "r"(a[mt][0]), "r"(a[mt][1]), "r"(a[mt][2]), "r"(a[mt][3]),
                          "r"(b0), "r"(b1));
                }
        }
    };

    load_stage(0, 0);
    asm volatile("cp.async.commit_group;");
    load_stage(1, 1);
    asm volatile("cp.async.commit_group;");

    #pragma unroll 1
    for (int kc = 0; kc < nch; kc++) {
        asm volatile("cp.async.wait_group 1;");
        __syncthreads();
        if (kc + 2 < nch) {
            load_stage(kc + 2, (kc + 2) % 3);
            asm volatile("cp.async.commit_group;");
        } else {
            asm volatile("cp.async.commit_group;");
        }
        compute(kc % 3);
    }

    #pragma unroll
    for (int mt = 0; mt < 4; mt++)
        #pragma unroll
        for (int nt = 0; nt < 4; nt++) {
            int row = m0 + wm * 64 + mt * 16 + (lane >> 2);
            int col = n0 + wn * 32 + nt * 8 + (lane & 3) * 2;
            if (MODE == 0) {
                if (row < M)
                    *(float2*)&C[(size_t)row * ldc + coff + col] =
                        make_float2(acc[mt][nt][0], acc[mt][nt][1]);
                if (row + 8 < M)
                    *(float2*)&C[(size_t)(row + 8) * ldc + coff + col] =
                        make_float2(acc[mt][nt][2], acc[mt][nt][3]);
            } else {
                const float* bias = (col < 256) ? bias_a : bias_s;
                __nv_bfloat16* dst = (col < 256) ? g_A2a : g_A2s;
                int lc = col & 255;
                float bv0 = bias[lc], bv1 = bias[lc + 1];
                #pragma unroll
                for (int half = 0; half < 2; half++) {
                    int r = row + half * 8;
                    if (r < M) {
                        float v0 = fmaxf(acc[mt][nt][half * 2]     + bv0, 0.f);
                        float v1 = fmaxf(acc[mt][nt][half * 2 + 1] + bv1, 0.f);
                        uint32_t hi, lo; split2(v0, v1, hi, lo);
                        *(uint32_t*)&dst[(size_t)r * 768 + lc]       = hi;
                        *(uint32_t*)&dst[(size_t)r * 768 + 256 + lc] = lo;
                        *(uint32_t*)&dst[(size_t)r * 768 + 512 + lc] = hi;
                    }
                }
            }
        }
}

// ---------------- Gram via bf16 tensor cores (mma.sync), SYMMETRIC -----------------
// 128x128 tiles, BK=64, 2-stage pipeline (proven round-11 shape), 2 CTA/SM.
// Transposed epilogue: single full-tile staging pass (pitch-130), 2 barriers total.
#define NT 79
#define NTILES (NT * (NT + 1) / 2)  // 3160
#define GBK 64
#define GSP 72                      // pitch: 64 bf16 + 8 pad (144B rows)
#define G_STG (128 * GSP)
#define GRAM_SMEM (2 * 2 * G_STG * 2)   // 73728 bytes
#define TP 130                      // full-tile transpose staging pitch (floats)

__global__ void __launch_bounds__(256, 2)
gram_mma(const __nv_bfloat16* __restrict__ Hb, float* __restrict__ C)
{
    extern __shared__ __align__(16) __nv_bfloat16 smem[];
    __nv_bfloat16* As = smem;                 // [2][G_STG]
    __nv_bfloat16* Bs = smem + 2 * G_STG;     // [2][G_STG]
    float* sT = (float*)smem;                 // reused after mainloop: [128][TP] = 66560 B

    // ---- map linear tile id -> (ti, tj) with ti <= tj ----
    int t = blockIdx.x;
    int ti = (int)((2.0f * NT + 1.0f -
                    sqrtf((2.0f * NT + 1.0f) * (2.0f * NT + 1.0f) - 8.0f * (float)t)) * 0.5f);
    if (ti < 0) ti = 0;
    if (ti > NT - 1) ti = NT - 1;
    #pragma unroll 1
    while (ti > 0 && (ti * NT - ti * (ti - 1) / 2) > t) ti--;
    #pragma unroll 1
    while (ti < NT - 1 && ((ti + 1) * NT - (ti + 1) * ti / 2) <= t) ti++;
    const int tj = ti + (t - (ti * NT - ti * (ti - 1) / 2));

    const int m0 = ti * 128;
    const int n0 = tj * 128;

    const int tid  = threadIdx.x;
    const int w    = tid >> 5;
    const int lane = tid & 31;
    const int wm   = w >> 2;
    const int wn   = w & 3;

    float acc[4][4][4];
    #pragma unroll
    for (int mt = 0; mt < 4; mt++)
        #pragma unroll
        for (int nt = 0; nt < 4; nt++)
            #pragma unroll
            for (int i = 0; i < 4; i++) acc[mt][nt][i] = 0.0f;

    // load one BK=64 chunk: A/B each 128 rows x 8 16B-chunks = 1024 cp.async
    auto load_stage = [&](int kc, int st) {
        #pragma unroll
        for (int i = 0; i < 4; i++) {
            int c = tid + i * 256;            // 0..1023
            int r = c >> 3, q = c & 7;
            {
                int grow = m0 + r;
                int rg = grow < NN ? grow : NN - 1;
                const __nv_bfloat16* src = Hb + (size_t)rg * 256 + kc * GBK + q * 8;
                uint32_t dst = (uint32_t)__cvta_generic_to_shared(&As[st * G_STG + r * GSP + q * 8]);
                asm volatile("cp.async.cg.shared.global [%0], [%1], 16;\n"
                             :: "r"(dst), "l"(src));
            }
            {
                int grow = n0 + r;
                int rg = grow < NN ? grow : NN - 1;
                const __nv_bfloat16* src = Hb + (size_t)rg * 256 + kc * GBK + q * 8;
                uint32_t dst = (uint32_t)__cvta_generic_to_shared(&Bs[st * G_STG + r * GSP + q * 8]);
                asm volatile("cp.async.cg.shared.global [%0], [%1], 16;\n"
                             :: "r"(dst), "l"(src));
            }
        }
    };

    auto compute = [&](int st) {
        #pragma unroll
        for (int ks = 0; ks < 4; ks++) {
            uint32_t a[4][4];
            #pragma unroll
            for (int mt = 0; mt < 4; mt++) {
                int row = wm * 64 + mt * 16 + (lane & 15);
                int col = ks * 16 + ((lane >> 4) << 3);
                uint32_t ad = (uint32_t)__cvta_generic_to_shared(&As[st * G_STG + row * GSP + col]);
                asm volatile("ldmatrix.sync.aligned.m8n8.x4.shared.b16 {%0,%1,%2,%3}, [%4];"
                             : "=r"(a[mt][0]), "=r"(a[mt][1]), "=r"(a[mt][2]), "=r"(a[mt][3])
                             : "r"(ad));
            }
            uint32_t b[2][4];
            #pragma unroll
            for (int p = 0; p < 2; p++) {
                int j = lane >> 3, l = lane & 7;
                int row = wn * 32 + p * 16 + ((j >> 1) << 3) + l;
                int col = ks * 16 + ((j & 1) << 3);
                uint32_t bd = (uint32_t)__cvta_generic_to_shared(&Bs[st * G_STG + row * GSP + col]);
                asm volatile("ldmatrix.sync.aligned.m8n8.x4.shared.b16 {%0,%1,%2,%3}, [%4];"
                             : "=r"(b[p][0]), "=r"(b[p][1]), "=r"(b[p][2]), "=r"(b[p][3])
                             : "r"(bd));
            }
            #pragma unroll
            for (int mt = 0; mt < 4; mt++)
                #pragma unroll
                for (int nt = 0; nt < 4; nt++) {
                    uint32_t b0 = b[nt >> 1][(nt & 1) * 2];
                    uint32_t b1 = b[nt >> 1][(nt & 1) * 2 + 1];
                    asm volatile(
                        "mma.sync.aligned.m16n8k16.row.col.f32.bf16.bf16.f32 "
                        "{%0,%1,%2,%3}, {%4,%5,%6,%7}, {%8,%9}, {%0,%1,%2,%3};"
                        : "+f"(acc[mt][nt][0]), "+f"(acc[mt][nt][1]),
                          "+f"(acc[mt][nt][2]), "+f"(acc[mt][nt][3])
                        : "r"(a[mt][0]), "r"(a[mt][1]), "r"(a[mt][2]), "r"(a[mt][3]),
                          "r"(b0), "r"(b1));
                }
        }
    };

    // double-buffered mainloop over 4 chunks
    load_stage(0, 0);
    asm volatile("cp.async.commit_group;");

    #pragma unroll 1
    for (int kc = 0; kc < 4; kc++) {
        if (kc + 1 < 4) {
            load_stage(kc + 1, (kc + 1) & 1);
            asm volatile("cp.async.commit_group;");
            asm volatile("cp.async.wait_group 1;");
        } else {
            asm volatile("cp.async.wait_group 0;");
        }
        __syncthreads();
        compute(kc & 1);
        __syncthreads();
    }

    // ---- direct write: C[m0 + rows, n0 + cols] ----
    #pragma unroll
    for (int mt = 0; mt < 4; mt++)
        #pragma unroll
        for (int nt = 0; nt < 4; nt++) {
            int row = m0 + wm * 64 + mt * 16 + (lane >> 2);
            int col = n0 + wn * 32 + nt * 8 + (lane & 3) * 2;
            if (col < NN) {
                if (row < NN)
                    *(float2*)&C[(size_t)row * NN + col] =
                        make_float2(acc[mt][nt][0], acc[mt][nt][1]);
                if (row + 8 < NN)
                    *(float2*)&C[(size_t)(row + 8) * NN + col] =
                        make_float2(acc[mt][nt][2], acc[mt][nt][3]);
            }
        }

    // ---- transposed write for off-diagonal tiles: single full-tile staging ----
    if (ti != tj) {
        __syncthreads();   // all warps done with As/Bs (mainloop) and direct write
        // stage ALL fragments transposed: sT[cloc][rloc], full 128x128
        #pragma unroll
        for (int mt = 0; mt < 4; mt++) {
            int rloc = wm * 64 + mt * 16 + (lane >> 2);   // 0..127
            #pragma unroll
            for (int nt = 0; nt < 4; nt++) {
                int cloc = wn * 32 + nt * 8 + (lane & 3) * 2;
                sT[(cloc)     * TP + rloc]     = acc[mt][nt][0];
                sT[(cloc + 1) * TP + rloc]     = acc[mt][nt][1];
                sT[(cloc)     * TP + rloc + 8] = acc[mt][nt][2];
                sT[(cloc + 1) * TP + rloc + 8] = acc[mt][nt][3];
            }
        }
        __syncthreads();
        // emit: 128 output rows (cc) x 128 cols (rr) = 4096 float4
        #pragma unroll
        for (int e = 0; e < 16; e++) {
            int idx = tid + 256 * e;       // 0..4095
            int cc  = idx >> 5;            // 0..127
            int rr  = (idx & 31) * 4;      // 0..124
            int grow = n0 + cc;
            int gcol = m0 + rr;
            if (grow < NN) {
                float4 v = make_float4(sT[cc * TP + rr],
                                       sT[cc * TP + rr + 1],
                                       sT[cc * TP + rr + 2],
                                       sT[cc * TP + rr + 3]);
                if (gcol + 3 < NN) {
                    *(float4*)&C[(size_t)grow * NN + gcol] = v;
                } else {
                    float vv[4] = {v.x, v.y, v.z, v.w};
                    #pragma unroll
                    for (int k = 0; k < 4; k++)
                        if (gcol + k < NN) C[(size_t)grow * NN + gcol + k] = vv[k];
                }
            }
        }
    }
}

// ---------------- launcher ----------------
extern "C" void kernel_launch(void* const* d_in, const int* in_sizes, int n_in,
                              void* d_out, int out_size)
{
    const float* h   = (const float*)d_in[0];
    const float* W1a = (const float*)d_in[1];
    const float* b1a = (const float*)d_in[2];
    const float* W2a = (const float*)d_in[3];
    const float* b2a = (const float*)d_in[4];
    const float* W1s = (const float*)d_in[5];
    const float* b1s = (const float*)d_in[6];
    const float* W2s = (const float*)d_in[7];
    const float* b2s = (const float*)d_in[8];
    const int*   ei  = (const int*)d_in[9];
    const int* src = ei;
    const int* dst = ei + NE;
    float* out = (float*)d_out;

    float* pXW2;
    __nv_bfloat16 *pHb, *pA1, *pA2a, *pA2s, *pWT1, *pWT2a, *pWT2s;
    int* pCnt;
    cudaGetSymbolAddress((void**)&pXW2,  g_XW2);
    cudaGetSymbolAddress((void**)&pHb,   g_Hb);
    cudaGetSymbolAddress((void**)&pA1,   g_A1);
    cudaGetSymbolAddress((void**)&pA2a,  g_A2a);
    cudaGetSymbolAddress((void**)&pA2s,  g_A2s);
    cudaGetSymbolAddress((void**)&pWT1,  g_WT1);
    cudaGetSymbolAddress((void**)&pWT2a, g_WT2a);
    cudaGetSymbolAddress((void**)&pWT2s, g_WT2s);
    cudaGetSymbolAddress((void**)&pCnt,  g_cnt);

    cudaFuncSetAttribute(gram_mma,   cudaFuncAttributeMaxDynamicSharedMemorySize, GRAM_SMEM);
    cudaFuncSetAttribute(gemm_bf<0>, cudaFuncAttributeMaxDynamicSharedMemorySize, GEMM_SMEM);
    cudaFuncSetAttribute(gemm_bf<1>, cudaFuncAttributeMaxDynamicSharedMemorySize, GEMM_SMEM);

    // graph prep + weight conversion
    cudaMemsetAsync(pCnt, 0, NN * sizeof(int));
    k_count<<<(NE + 255) / 256, 256>>>(dst);
    k_scan <<<1, 1024>>>();
    k_fill <<<(NE + 255) / 256, 256>>>(src, dst);
    k_split_w<<<768, 256>>>(W1a, W1s, W2a, W2s);

    // layer 1 (aggregate-first): hagg = A_norm@h -> A1; H1 = relu(hagg@W1+b) -> A2a/A2s
    k_agg_h<<<NN, 32>>>((const float4*)h);
    gemm_bf<1><<<dim3(4, NT), 256, GEMM_SMEM>>>(pA1, pWT1, nullptr, nullptr, 384,
                                                nullptr, 0, NN, b1a, b1s);

    // layer 2 (transform-first), both branches in ONE launch
    gemm_bf<0><<<dim3(2, NT), 256, GEMM_SMEM>>>(pA2a, pWT2a, pA2s, pWT2s, 768,
                                                pXW2, 256, NN, nullptr, nullptr);
    k_agg2<<<NN, 64>>>((const float4*)pXW2, out, pHb, b2a, b2s);

    // s_ = h_ @ h_^T: symmetric 128x128 tiles, BK=64, double-buffered
    gram_mma<<<NTILES, 256, GRAM_SMEM>>>(pHb, out + S_OFF);

    // h passthrough
    cudaMemcpyAsync(out + H_OFF, h, (size_t)NN * 128 * sizeof(float),
                    cudaMemcpyDeviceToDevice);
}

// round 15
// speedup vs baseline: 1.0033x; 1.0013x over previous
#include <cuda_runtime.h>
#include <cuda_bf16.h>
#include <cstdint>

// Problem constants
#define NN   10000
#define NE   320000
#define F2   256     // 2*OUT

// Output layout: x_ [NN*128], s_ [NN*NN], h [NN*128]
#define S_OFF  (NN * 128)
#define H_OFF  (S_OFF + (size_t)NN * NN)

// ---------------- static device scratch (no allocs allowed) ----------------
__device__ float g_XW2[NN * F2];              // H1 @ [W2a | W2s] (fp32, gathered by agg2)
__device__ __nv_bfloat16 g_A1 [NN * 384];     // agg(h) split: [hi | lo | hi]    (K=384)
__device__ __nv_bfloat16 g_A2a[NN * 768];     // H1a split: [hi | lo | hi]       (K=768)
__device__ __nv_bfloat16 g_A2s[NN * 768];     // H1s split
__device__ __nv_bfloat16 g_WT1 [512 * 384];   // [W1a|W1s]^T split: [whi | whi | wlo]
__device__ __nv_bfloat16 g_WT2a[128 * 768];   // W2a^T split
__device__ __nv_bfloat16 g_WT2s[128 * 768];   // W2s^T split
__device__ __nv_bfloat16 g_Hb[NN * 256];      // h_ split: cols [0,128)=hi, [128,256)=lo
__device__ float g_dinv[NN];
__device__ int   g_cnt[NN];
__device__ int   g_cur[NN];
__device__ int   g_rowptr[NN + 1];
__device__ int   g_col[NE];

// ---------------- graph preprocessing ----------------
__global__ void k_count(const int* __restrict__ dst) {
    int e = blockIdx.x * 256 + threadIdx.x;
    if (e < NE) atomicAdd(&g_cnt[dst[e]], 1);
}

// scan cnt -> rowptr (also seeds g_cur = rowptr), AND compute dinv (fused)
__global__ void k_scan() {
    __shared__ int s[1024];
    int t = threadIdx.x;
    const int CH = 10;
    int base = t * CH;
    int sum = 0;
    #pragma unroll
    for (int i = 0; i < CH; i++) { int idx = base + i; if (idx < NN) sum += g_cnt[idx]; }
    s[t] = sum;
    __syncthreads();
    for (int off = 1; off < 1024; off <<= 1) {
        int v = (t >= off) ? s[t - off] : 0;
        __syncthreads();
        s[t] += v;
        __syncthreads();
    }
    int run = (t > 0) ? s[t - 1] : 0;
    #pragma unroll
    for (int i = 0; i < CH; i++) {
        int idx = base + i;
        if (idx < NN) {
            g_rowptr[idx] = run;
            g_cur[idx]    = run;
            int c = g_cnt[idx];
            run += c;
            g_dinv[idx] = rsqrtf(1.0f + (float)c);
        }
    }
    if (t == 1023) g_rowptr[NN] = s[1023];
}

__global__ void k_fill(const int* __restrict__ src, const int* __restrict__ dst) {
    int e = blockIdx.x * 256 + threadIdx.x;
    if (e < NE) {
        int d = dst[e];
        int pos = atomicAdd(&g_cur[d], 1);
        g_col[pos] = src[e];
    }
}

// ---------------- split helpers ----------------
struct alignas(8) bf4 { __nv_bfloat162 a, b; };

__device__ __forceinline__ void split4(float4 v, bf4& hv, bf4& lv) {
    __nv_bfloat16 h0 = __float2bfloat16(v.x), h1 = __float2bfloat16(v.y);
    __nv_bfloat16 h2 = __float2bfloat16(v.z), h3 = __float2bfloat16(v.w);
    __nv_bfloat16 l0 = __float2bfloat16(v.x - __bfloat162float(h0));
    __nv_bfloat16 l1 = __float2bfloat16(v.y - __bfloat162float(h1));
    __nv_bfloat16 l2 = __float2bfloat16(v.z - __bfloat162float(h2));
    __nv_bfloat16 l3 = __float2bfloat16(v.w - __bfloat162float(h3));
    hv.a = __nv_bfloat162(h0, h1); hv.b = __nv_bfloat162(h2, h3);
    lv.a = __nv_bfloat162(l0, l1); lv.b = __nv_bfloat162(l2, l3);
}

__device__ __forceinline__ void split2(float v0, float v1, uint32_t& hi, uint32_t& lo) {
    __nv_bfloat16 h0 = __float2bfloat16(v0), h1 = __float2bfloat16(v1);
    __nv_bfloat16 l0 = __float2bfloat16(v0 - __bfloat162float(h0));
    __nv_bfloat16 l1 = __float2bfloat16(v1 - __bfloat162float(h1));
    __nv_bfloat162 hp(h0, h1), lp(l0, l1);
    hi = *(uint32_t*)&hp; lo = *(uint32_t*)&lp;
}

// Merged weight split: blocks [0,512) -> WT1 rows; blocks [512,768) -> WT2 a/s.
__global__ void k_split_w(const float* __restrict__ W1a, const float* __restrict__ W1s,
                          const float* __restrict__ W2a, const float* __restrict__ W2s)
{
    int b = blockIdx.x;
    int k = threadIdx.x;   // 0..255
    if (b < 512) {
        if (k >= 128) return;
        const float* W = (b < 256) ? W1a : W1s;
        int col = b & 255;
        float v = W[k * 256 + col];
        __nv_bfloat16 hi = __float2bfloat16(v);
        __nv_bfloat16 lo = __float2bfloat16(v - __bfloat162float(hi));
        g_WT1[(size_t)b * 384 + k]       = hi;
        g_WT1[(size_t)b * 384 + 128 + k] = hi;
        g_WT1[(size_t)b * 384 + 256 + k] = lo;
    } else {
        int n = (b - 512) & 127;
        int which = (b - 512) >> 7;   // 0: W2a, 1: W2s
        const float* W = which ? W2s : W2a;
        __nv_bfloat16* dst = which ? g_WT2s : g_WT2a;
        float v = W[k * 128 + n];
        __nv_bfloat16 hi = __float2bfloat16(v);
        __nv_bfloat16 lo = __float2bfloat16(v - __bfloat162float(hi));
        dst[(size_t)n * 768 + k]       = hi;
        dst[(size_t)n * 768 + 256 + k] = hi;
        dst[(size_t)n * 768 + 512 + k] = lo;
    }
}

// ---------------- layer-1 aggregation of RAW features ---------------------------
// 128 threads = 4 warps; warp w handles node blockIdx.x*4 + w (lane = feature chunk)
__global__ void k_agg_h(const float4* __restrict__ h4) {
    int n = blockIdx.x * 4 + (threadIdx.x >> 5);
    if (n >= NN) return;
    int t = threadIdx.x & 31;   // 32 lanes, float4 each = 128 features
    float di = g_dinv[n];
    float4 x = h4[(size_t)n * 32 + t];
    float w0 = di * di;
    float4 a0 = make_float4(x.x * w0, x.y * w0, x.z * w0, x.w * w0);
    float4 a1 = make_float4(0.f, 0.f, 0.f, 0.f);
    float4 a2 = make_float4(0.f, 0.f, 0.f, 0.f);
    float4 a3 = make_float4(0.f, 0.f, 0.f, 0.f);

    int e0 = g_rowptr[n], e1 = g_rowptr[n + 1];
    int e = e0;
    for (; e + 4 <= e1; e += 4) {
        int s0 = g_col[e], s1 = g_col[e + 1], s2 = g_col[e + 2], s3 = g_col[e + 3];
        float ws0 = g_dinv[s0] * di, ws1 = g_dinv[s1] * di;
        float ws2 = g_dinv[s2] * di, ws3 = g_dinv[s3] * di;
        float4 v0 = h4[(size_t)s0 * 32 + t];
        float4 v1 = h4[(size_t)s1 * 32 + t];
        float4 v2 = h4[(size_t)s2 * 32 + t];
        float4 v3 = h4[(size_t)s3 * 32 + t];
        a0.x += v0.x * ws0; a0.y += v0.y * ws0; a0.z += v0.z * ws0; a0.w += v0.w * ws0;
        a1.x += v1.x * ws1; a1.y += v1.y * ws1; a1.z += v1.z * ws1; a1.w += v1.w * ws1;
        a2.x += v2.x * ws2; a2.y += v2.y * ws2; a2.z += v2.z * ws2; a2.w += v2.w * ws2;
        a3.x += v3.x * ws3; a3.y += v3.y * ws3; a3.z += v3.z * ws3; a3.w += v3.w * ws3;
    }
    for (; e < e1; e++) {
        int s = g_col[e];
        float ws = g_dinv[s] * di;
        float4 v = h4[(size_t)s * 32 + t];
        a0.x += v.x * ws; a0.y += v.y * ws; a0.z += v.z * ws; a0.w += v.w * ws;
    }
    float4 acc = make_float4(a0.x + a1.x + a2.x + a3.x, a0.y + a1.y + a2.y + a3.y,
                             a0.z + a1.z + a2.z + a3.z, a0.w + a1.w + a2.w + a3.w);
    bf4 hv, lv; split4(acc, hv, lv);
    int c = t * 4;
    *(bf4*)&g_A1[(size_t)n * 384 + c]       = hv;
    *(bf4*)&g_A1[(size_t)n * 384 + 128 + c] = lv;
    *(bf4*)&g_A1[(size_t)n * 384 + 256 + c] = hv;
}

// ---------------- GCN aggregation layer 2 ----------------------------------------
// 128 threads; half-block (64 threads) per node: node = blockIdx.x*2 + (tid>>6)
__global__ void k_agg2(const float4* __restrict__ XW4,   // [NN][64] float4 (F2=256)
                       float* __restrict__ xout,          // [NN][128]
                       __nv_bfloat16* __restrict__ Hb,    // [NN][256] hi|lo
                       const float* __restrict__ b2a, const float* __restrict__ b2s)
{
    int n = blockIdx.x * 2 + (threadIdx.x >> 6);
    if (n >= NN) return;
    int t = threadIdx.x & 63;   // 64 lanes, float4 each = 256 features
    float di = g_dinv[n];
    float4 x = XW4[(size_t)n * 64 + t];
    float w0 = di * di;
    float4 a0 = make_float4(x.x * w0, x.y * w0, x.z * w0, x.w * w0);
    float4 a1 = make_float4(0.f, 0.f, 0.f, 0.f);
    float4 a2 = make_float4(0.f, 0.f, 0.f, 0.f);
    float4 a3 = make_float4(0.f, 0.f, 0.f, 0.f);

    int e0 = g_rowptr[n], e1 = g_rowptr[n + 1];
    int e = e0;
    for (; e + 4 <= e1; e += 4) {
        int s0 = g_col[e], s1 = g_col[e + 1], s2 = g_col[e + 2], s3 = g_col[e + 3];
        float ws0 = g_dinv[s0] * di, ws1 = g_dinv[s1] * di;
        float ws2 = g_dinv[s2] * di, ws3 = g_dinv[s3] * di;
        float4 v0 = XW4[(size_t)s0 * 64 + t];
        float4 v1 = XW4[(size_t)s1 * 64 + t];
        float4 v2 = XW4[(size_t)s2 * 64 + t];
        float4 v3 = XW4[(size_t)s3 * 64 + t];
        a0.x += v0.x * ws0; a0.y += v0.y * ws0; a0.z += v0.z * ws0; a0.w += v0.w * ws0;
        a1.x += v1.x * ws1; a1.y += v1.y * ws1; a1.z += v1.z * ws1; a1.w += v1.w * ws1;
        a2.x += v2.x * ws2; a2.y += v2.y * ws2; a2.z += v2.z * ws2; a2.w += v2.w * ws2;
        a3.x += v3.x * ws3; a3.y += v3.y * ws3; a3.z += v3.z * ws3; a3.w += v3.w * ws3;
    }
    for (; e < e1; e++) {
        int s = g_col[e];
        float ws = g_dinv[s] * di;
        float4 v = XW4[(size_t)s * 64 + t];
        a0.x += v.x * ws; a0.y += v.y * ws; a0.z += v.z * ws; a0.w += v.w * ws;
    }
    float4 acc = make_float4(a0.x + a1.x + a2.x + a3.x, a0.y + a1.y + a2.y + a3.y,
                             a0.z + a1.z + a2.z + a3.z, a0.w + a1.w + a2.w + a3.w);

    int c = t * 4;
    if (c < 128) {
        float4 bv = *(const float4*)&b2a[c];
        acc.x += bv.x; acc.y += bv.y; acc.z += bv.z; acc.w += bv.w;
        *(float4*)&xout[(size_t)n * 128 + c] = acc;
    } else {
        int cc = c - 128;
        float4 bv = *(const float4*)&b2s[cc];
        acc.x += bv.x; acc.y += bv.y; acc.z += bv.z; acc.w += bv.w;
        bf4 hv, lv; split4(acc, hv, lv);
        *(bf4*)&Hb[(size_t)n * 256 + cc]       = hv;
        *(bf4*)&Hb[(size_t)n * 256 + 128 + cc] = lv;
    }
}

// ---------------- bf16 tensor-core GEMM: C[M,N] = A[M,K] @ B[N,K]^T ----------------
// (proven shape: 128x128 tile, BK=32, 3-stage, 2 CTA/SM)
#define BK 32
#define SP 40
#define STG_ELE (128 * SP)
#define GEMM_SMEM (3 * 2 * STG_ELE * 2)   // 61440 bytes

template <int MODE>
__global__ void __launch_bounds__(256, 2)
gemm_bf(const __nv_bfloat16* __restrict__ A, const __nv_bfloat16* __restrict__ B,
        const __nv_bfloat16* __restrict__ A2, const __nv_bfloat16* __restrict__ B2,
        int K, float* __restrict__ C, int ldc, int M,
        const float* __restrict__ bias_a, const float* __restrict__ bias_s)
{
    extern __shared__ __align__(16) __nv_bfloat16 smem[];
    __nv_bfloat16* As = smem;
    __nv_bfloat16* Bs = smem + 3 * STG_ELE;

    const int tid  = threadIdx.x;
    const int m0   = blockIdx.y * 128;
    const __nv_bfloat16* Ap = A;
    const __nv_bfloat16* Bp = B;
    int n0, coff;
    if (MODE == 0) {
        if (blockIdx.x) { Ap = A2; Bp = B2; }
        n0 = 0; coff = blockIdx.x * 128;
    } else {
        n0 = blockIdx.x * 128; coff = 0;
    }
    const int w    = tid >> 5;
    const int lane = tid & 31;
    const int wm   = w >> 2;
    const int wn   = w & 3;
    const int nch  = K / BK;

    float acc[4][4][4];
    #pragma unroll
    for (int mt = 0; mt < 4; mt++)
        #pragma unroll
        for (int nt = 0; nt < 4; nt++)
            #pragma unroll
            for (int i = 0; i < 4; i++) acc[mt][nt][i] = 0.0f;

    auto load_stage = [&](int kc, int st) {
        #pragma unroll
        for (int i = 0; i < 2; i++) {
            int c = tid + i * 256;
            int r = c >> 2, q = c & 3;
            {
                int grow = m0 + r;
                int rg = grow < M ? grow : M - 1;
                const __nv_bfloat16* src = Ap + (size_t)rg * K + kc * BK + q * 8;
                uint32_t dst = (uint32_t)__cvta_generic_to_shared(&As[st * STG_ELE + r * SP + q * 8]);
                asm volatile("cp.async.cg.shared.global [%0], [%1], 16;\n"
                             :: "r"(dst), "l"(src));
            }
            {
                const __nv_bfloat16* src = Bp + (size_t)(n0 + r) * K + kc * BK + q * 8;
                uint32_t dst = (uint32_t)__cvta_generic_to_shared(&Bs[st * STG_ELE + r * SP + q * 8]);
                asm volatile("cp.async.cg.shared.global [%0], [%1], 16;\n"
                             :: "r"(dst), "l"(src));
            }
        }
    };

    auto compute = [&](int st) {
        #pragma unroll
        for (int ks = 0; ks < 2; ks++) {
            uint32_t a[4][4];
            #pragma unroll
            for (int mt = 0; mt < 4; mt++) {
                int row = wm * 64 + mt * 16 + (lane & 15);
                int col = ks * 16 + ((lane >> 4) << 3);
                uint32_t ad = (uint32_t)__cvta_generic_to_shared(&As[st * STG_ELE + row * SP + col]);
                asm volatile("ldmatrix.sync.aligned.m8n8.x4.shared.b16 {%0,%1,%2,%3}, [%4];"
                             : "=r"(a[mt][0]), "=r"(a[mt][1]), "=r"(a[mt][2]), "=r"(a[mt][3])
                             : "r"(ad));
            }
            uint32_t b[2][4];
            #pragma unroll
            for (int p = 0; p < 2; p++) {
                int j = lane >> 3, l = lane & 7;
                int row = wn * 32 + p * 16 + ((j >> 1) << 3) + l;
                int col = ks * 16 + ((j & 1) << 3);
                uint32_t bd = (uint32_t)__cvta_generic_to_shared(&Bs[st * STG_ELE + row * SP + col]);
                asm volatile("ldmatrix.sync.aligned.m8n8.x4.shared.b16 {%0,%1,%2,%3}, [%4];"
                             : "=r"(b[p][0]), "=r"(b[p][1]), "=r"(b[p][2]), "=r"(b[p][3])
                             : "r"(bd));
            }
            #pragma unroll
            for (int mt = 0; mt < 4; mt++)
                #pragma unroll
                for (int nt = 0; nt < 4; nt++) {
                    uint32_t b0 = b[nt >> 1][(nt & 1) * 2];
                    uint32_t b1 = b[nt >> 1][(nt & 1) * 2 + 1];
                    asm volatile(
                        "mma.sync.aligned.m16n8k16.row.col.f32.bf16.bf16.f32 "
                        "{%0,%1,%2,%3}, {%4,%5,%6,%7}, {%8,%9}, {%0,%1,%2,%3};"
                        : "+f"(acc[mt][nt][0]), "+f"(acc[mt][nt][1]),
                          "+f"(acc[mt][nt][2]), "+f"(acc[mt][nt][3])
                        : "r"(a[mt][0]), "r"(a[mt][1]), "r"(a[mt][2]), "r"(a[mt][3]),
                          "r"(b0), "r"(b1));
                }
        }
    };

    load_stage(0, 0);
    asm volatile("cp.async.commit_group;");
    load_stage(1, 1);
    asm volatile("cp.async.commit_group;");

    #pragma unroll 1
    for (int kc = 0; kc < nch; kc++) {
        asm volatile("cp.async.wait_group 1;");
        __syncthreads();
        if (kc + 2 < nch) {
            load_stage(kc + 2, (kc + 2) % 3);
            asm volatile("cp.async.commit_group;");
        } else {
            asm volatile("cp.async.commit_group;");
        }
        compute(kc % 3);
    }

    #pragma unroll
    for (int mt = 0; mt < 4; mt++)
        #pragma unroll
        for (int nt = 0; nt < 4; nt++) {
            int row = m0 + wm * 64 + mt * 16 + (lane >> 2);
            int col = n0 + wn * 32 + nt * 8 + (lane & 3) * 2;
            if (MODE == 0) {
                if (row < M)
                    *(float2*)&C[(size_t)row * ldc + coff + col] =
                        make_float2(acc[mt][nt][0], acc[mt][nt][1]);
                if (row + 8 < M)
                    *(float2*)&C[(size_t)(row + 8) * ldc + coff + col] =
                        make_float2(acc[mt][nt][2], acc[mt][nt][3]);
            } else {
                const float* bias = (col < 256) ? bias_a : bias_s;
                __nv_bfloat16* dst = (col < 256) ? g_A2a : g_A2s;
                int lc = col & 255;
                float bv0 = bias[lc], bv1 = bias[lc + 1];
                #pragma unroll
                for (int half = 0; half < 2; half++) {
                    int r = row + half * 8;
                    if (r < M) {
                        float v0 = fmaxf(acc[mt][nt][half * 2]     + bv0, 0.f);
                        float v1 = fmaxf(acc[mt][nt][half * 2 + 1] + bv1, 0.f);
                        uint32_t hi, lo; split2(v0, v1, hi, lo);
                        *(uint32_t*)&dst[(size_t)r * 768 + lc]       = hi;
                        *(uint32_t*)&dst[(size_t)r * 768 + 256 + lc] = lo;
                        *(uint32_t*)&dst[(size_t)r * 768 + 512 + lc] = hi;
                    }
                }
            }
        }
}

// ---------------- Gram via bf16 tensor cores (mma.sync), SYMMETRIC -----------------
// 128x128 tiles, BK=64, 2-stage pipeline, 2 CTA/SM, single-pass transpose epilogue.
#define NT 79
#define NTILES (NT * (NT + 1) / 2)  // 3160
#define GBK 64
#define GSP 72                      // pitch: 64 bf16 + 8 pad (144B rows)
#define G_STG (128 * GSP)
#define GRAM_SMEM (2 * 2 * G_STG * 2)   // 73728 bytes
#define TP 130                      // full-tile transpose staging pitch (floats)

__global__ void __launch_bounds__(256, 2)
gram_mma(const __nv_bfloat16* __restrict__ Hb, float* __restrict__ C)
{
    extern __shared__ __align__(16) __nv_bfloat16 smem[];
    __nv_bfloat16* As = smem;                 // [2][G_STG]
    __nv_bfloat16* Bs = smem + 2 * G_STG;     // [2][G_STG]
    float* sT = (float*)smem;                 // reused after mainloop: [128][TP]

    // ---- map linear tile id -> (ti, tj) with ti <= tj ----
    int t = blockIdx.x;
    int ti = (int)((2.0f * NT + 1.0f -
                    sqrtf((2.0f * NT + 1.0f) * (2.0f * NT + 1.0f) - 8.0f * (float)t)) * 0.5f);
    if (ti < 0) ti = 0;
    if (ti > NT - 1) ti = NT - 1;
    #pragma unroll 1
    while (ti > 0 && (ti * NT - ti * (ti - 1) / 2) > t) ti--;
    #pragma unroll 1
    while (ti < NT - 1 && ((ti + 1) * NT - (ti + 1) * ti / 2) <= t) ti++;
    const int tj = ti + (t - (ti * NT - ti * (ti - 1) / 2));

    const int m0 = ti * 128;
    const int n0 = tj * 128;

    const int tid  = threadIdx.x;
    const int w    = tid >> 5;
    const int lane = tid & 31;
    const int wm   = w >> 2;
    const int wn   = w & 3;

    float acc[4][4][4];
    #pragma unroll
    for (int mt = 0; mt < 4; mt++)
        #pragma unroll
        for (int nt = 0; nt < 4; nt++)
            #pragma unroll
            for (int i = 0; i < 4; i++) acc[mt][nt][i] = 0.0f;

    auto load_stage = [&](int kc, int st) {
        #pragma unroll
        for (int i = 0; i < 4; i++) {
            int c = tid + i * 256;            // 0..1023
            int r = c >> 3, q = c & 7;
            {
                int grow = m0 + r;
                int rg = grow < NN ? grow : NN - 1;
                const __nv_bfloat16* src = Hb + (size_t)rg * 256 + kc * GBK + q * 8;
                uint32_t dst = (uint32_t)__cvta_generic_to_shared(&As[st * G_STG + r * GSP + q * 8]);
                asm volatile("cp.async.cg.shared.global [%0], [%1], 16;\n"
                             :: "r"(dst), "l"(src));
            }
            {
                int grow = n0 + r;
                int rg = grow < NN ? grow : NN - 1;
                const __nv_bfloat16* src = Hb + (size_t)rg * 256 + kc * GBK + q * 8;
                uint32_t dst = (uint32_t)__cvta_generic_to_shared(&Bs[st * G_STG + r * GSP + q * 8]);
                asm volatile("cp.async.cg.shared.global [%0], [%1], 16;\n"
                             :: "r"(dst), "l"(src));
            }
        }
    };

    auto compute = [&](int st) {
        #pragma unroll
        for (int ks = 0; ks < 4; ks++) {
            uint32_t a[4][4];
            #pragma unroll
            for (int mt = 0; mt < 4; mt++) {
                int row = wm * 64 + mt * 16 + (lane & 15);
                int col = ks * 16 + ((lane >> 4) << 3);
                uint32_t ad = (uint32_t)__cvta_generic_to_shared(&As[st * G_STG + row * GSP + col]);
                asm volatile("ldmatrix.sync.aligned.m8n8.x4.shared.b16 {%0,%1,%2,%3}, [%4];"
                             : "=r"(a[mt][0]), "=r"(a[mt][1]), "=r"(a[mt][2]), "=r"(a[mt][3])
                             : "r"(ad));
            }
            uint32_t b[2][4];
            #pragma unroll
            for (int p = 0; p < 2; p++) {
                int j = lane >> 3, l = lane & 7;
                int row = wn * 32 + p * 16 + ((j >> 1) << 3) + l;
                int col = ks * 16 + ((j & 1) << 3);
                uint32_t bd = (uint32_t)__cvta_generic_to_shared(&Bs[st * G_STG + row * GSP + col]);
                asm volatile("ldmatrix.sync.aligned.m8n8.x4.shared.b16 {%0,%1,%2,%3}, [%4];"
                             : "=r"(b[p][0]), "=r"(b[p][1]), "=r"(b[p][2]), "=r"(b[p][3])
                             : "r"(bd));
            }
            #pragma unroll
            for (int mt = 0; mt < 4; mt++)
                #pragma unroll
                for (int nt = 0; nt < 4; nt++) {
                    uint32_t b0 = b[nt >> 1][(nt & 1) * 2];
                    uint32_t b1 = b[nt >> 1][(nt & 1) * 2 + 1];
                    asm volatile(
                        "mma.sync.aligned.m16n8k16.row.col.f32.bf16.bf16.f32 "
                        "{%0,%1,%2,%3}, {%4,%5,%6,%7}, {%8,%9}, {%0,%1,%2,%3};"
                        : "+f"(acc[mt][nt][0]), "+f"(acc[mt][nt][1]),
                          "+f"(acc[mt][nt][2]), "+f"(acc[mt][nt][3])
                        : "r"(a[mt][0]), "r"(a[mt][1]), "r"(a[mt][2]), "r"(a[mt][3]),
                          "r"(b0), "r"(b1));
                }
        }
    };

    // double-buffered mainloop over 4 chunks
    load_stage(0, 0);
    asm volatile("cp.async.commit_group;");

    #pragma unroll 1
    for (int kc = 0; kc < 4; kc++) {
        if (kc + 1 < 4) {
            load_stage(kc + 1, (kc + 1) & 1);
            asm volatile("cp.async.commit_group;");
            asm volatile("cp.async.wait_group 1;");
        } else {
            asm volatile("cp.async.wait_group 0;");
        }
        __syncthreads();
        compute(kc & 1);
        __syncthreads();
    }

    // ---- direct write: C[m0 + rows, n0 + cols] ----
    #pragma unroll
    for (int mt = 0; mt < 4; mt++)
        #pragma unroll
        for (int nt = 0; nt < 4; nt++) {
            int row = m0 + wm * 64 + mt * 16 + (lane >> 2);
            int col = n0 + wn * 32 + nt * 8 + (lane & 3) * 2;
            if (col < NN) {
                if (row < NN)
                    *(float2*)&C[(size_t)row * NN + col] =
                        make_float2(acc[mt][nt][0], acc[mt][nt][1]);
                if (row + 8 < NN)
                    *(float2*)&C[(size_t)(row + 8) * NN + col] =
                        make_float2(acc[mt][nt][2], acc[mt][nt][3]);
            }
        }

    // ---- transposed write for off-diagonal tiles: single full-tile staging ----
    if (ti != tj) {
        __syncthreads();
        #pragma unroll
        for (int mt = 0; mt < 4; mt++) {
            int rloc = wm * 64 + mt * 16 + (lane >> 2);   // 0..127
            #pragma unroll
            for (int nt = 0; nt < 4; nt++) {
                int cloc = wn * 32 + nt * 8 + (lane & 3) * 2;
                sT[(cloc)     * TP + rloc]     = acc[mt][nt][0];
                sT[(cloc + 1) * TP + rloc]     = acc[mt][nt][1];
                sT[(cloc)     * TP + rloc + 8] = acc[mt][nt][2];
                sT[(cloc + 1) * TP + rloc + 8] = acc[mt][nt][3];
            }
        }
        __syncthreads();
        #pragma unroll
        for (int e = 0; e < 16; e++) {
            int idx = tid + 256 * e;       // 0..4095
            int cc  = idx >> 5;            // 0..127
            int rr  = (idx & 31) * 4;      // 0..124
            int grow = n0 + cc;
            int gcol = m0 + rr;
            if (grow < NN) {
                float4 v = make_float4(sT[cc * TP + rr],
                                       sT[cc * TP + rr + 1],
                                       sT[cc * TP + rr + 2],
                                       sT[cc * TP + rr + 3]);
                if (gcol + 3 < NN) {
                    *(float4*)&C[(size_t)grow * NN + gcol] = v;
                } else {
                    float vv[4] = {v.x, v.y, v.z, v.w};
                    #pragma unroll
                    for (int k = 0; k < 4; k++)
                        if (gcol + k < NN) C[(size_t)grow * NN + gcol + k] = vv[k];
                }
            }
        }
    }
}

// ---------------- launcher ----------------
extern "C" void kernel_launch(void* const* d_in, const int* in_sizes, int n_in,
                              void* d_out, int out_size)
{
    const float* h   = (const float*)d_in[0];
    const float* W1a = (const float*)d_in[1];
    const float* b1a = (const float*)d_in[2];
    const float* W2a = (const float*)d_in[3];
    const float* b2a = (const float*)d_in[4];
    const float* W1s = (const float*)d_in[5];
    const float* b1s = (const float*)d_in[6];
    const float* W2s = (const float*)d_in[7];
    const float* b2s = (const float*)d_in[8];
    const int*   ei  = (const int*)d_in[9];
    const int* src = ei;
    const int* dst = ei + NE;
    float* out = (float*)d_out;

    float* pXW2;
    __nv_bfloat16 *pHb, *pA1, *pA2a, *pA2s, *pWT1, *pWT2a, *pWT2s;
    int* pCnt;
    cudaGetSymbolAddress((void**)&pXW2,  g_XW2);
    cudaGetSymbolAddress((void**)&pHb,   g_Hb);
    cudaGetSymbolAddress((void**)&pA1,   g_A1);
    cudaGetSymbolAddress((void**)&pA2a,  g_A2a);
    cudaGetSymbolAddress((void**)&pA2s,  g_A2s);
    cudaGetSymbolAddress((void**)&pWT1,  g_WT1);
    cudaGetSymbolAddress((void**)&pWT2a, g_WT2a);
    cudaGetSymbolAddress((void**)&pWT2s, g_WT2s);
    cudaGetSymbolAddress((void**)&pCnt,  g_cnt);

    cudaFuncSetAttribute(gram_mma,   cudaFuncAttributeMaxDynamicSharedMemorySize, GRAM_SMEM);
    cudaFuncSetAttribute(gemm_bf<0>, cudaFuncAttributeMaxDynamicSharedMemorySize, GEMM_SMEM);
    cudaFuncSetAttribute(gemm_bf<1>, cudaFuncAttributeMaxDynamicSharedMemorySize, GEMM_SMEM);

    // graph prep + weight conversion
    cudaMemsetAsync(pCnt, 0, NN * sizeof(int));
    k_count<<<(NE + 255) / 256, 256>>>(dst);
    k_scan <<<1, 1024>>>();
    k_fill <<<(NE + 255) / 256, 256>>>(src, dst);
    k_split_w<<<768, 256>>>(W1a, W1s, W2a, W2s);

    // layer 1 (aggregate-first): hagg = A_norm@h -> A1; H1 = relu(hagg@W1+b) -> A2a/A2s
    k_agg_h<<<(NN + 3) / 4, 128>>>((const float4*)h);
    gemm_bf<1><<<dim3(4, NT), 256, GEMM_SMEM>>>(pA1, pWT1, nullptr, nullptr, 384,
                                                nullptr, 0, NN, b1a, b1s);

    // layer 2 (transform-first), both branches in ONE launch
    gemm_bf<0><<<dim3(2, NT), 256, GEMM_SMEM>>>(pA2a, pWT2a, pA2s, pWT2s, 768,
                                                pXW2, 256, NN, nullptr, nullptr);
    k_agg2<<<(NN + 1) / 2, 128>>>((const float4*)pXW2, out, pHb, b2a, b2s);

    // s_ = h_ @ h_^T: symmetric 128x128 tiles, BK=64, double-buffered
    gram_mma<<<NTILES, 256, GRAM_SMEM>>>(pHb, out + S_OFF);

    // h passthrough
    cudaMemcpyAsync(out + H_OFF, h, (size_t)NN * 128 * sizeof(float),
                    cudaMemcpyDeviceToDevice);
}

// round 16
// speedup vs baseline: 1.0401x; 1.0367x over previous
#include <cuda_runtime.h>
#include <cuda_bf16.h>
#include <cstdint>

// Problem constants
#define NN   10000
#define NE   320000
#define F2   256     // 2*OUT

// Output layout: x_ [NN*128], s_ [NN*NN], h [NN*128]
#define S_OFF  (NN * 128)
#define H_OFF  (S_OFF + (size_t)NN * NN)

// ---------------- static device scratch (no allocs allowed) ----------------
__device__ float g_XW2[NN * F2];              // H1 @ [W2a | W2s] (fp32, gathered by agg2)
__device__ __nv_bfloat16 g_A1 [NN * 384];     // agg(h) split: [hi | lo | hi]    (K=384)
__device__ __nv_bfloat16 g_A2a[NN * 768];     // H1a split: [hi | lo | hi]       (K=768)
__device__ __nv_bfloat16 g_A2s[NN * 768];     // H1s split
__device__ __nv_bfloat16 g_WT1 [512 * 384];   // [W1a|W1s]^T split: [whi | whi | wlo]
__device__ __nv_bfloat16 g_WT2a[128 * 768];   // W2a^T split
__device__ __nv_bfloat16 g_WT2s[128 * 768];   // W2s^T split
__device__ __nv_bfloat16 g_Hb[NN * 256];      // h_ split: cols [0,128)=hi, [128,256)=lo
__device__ float g_dinv[NN];
__device__ int   g_cnt[NN];
__device__ int   g_cur[NN];
__device__ int   g_rowptr[NN + 1];
__device__ int   g_col[NE];

// ---------------- graph preprocessing ----------------
__global__ void k_count(const int* __restrict__ dst) {
    int e = blockIdx.x * 256 + threadIdx.x;
    if (e < NE) atomicAdd(&g_cnt[dst[e]], 1);
}

// scan cnt -> rowptr (also seeds g_cur = rowptr), AND compute dinv (fused)
__global__ void k_scan() {
    __shared__ int s[1024];
    int t = threadIdx.x;
    const int CH = 10;
    int base = t * CH;
    int sum = 0;
    #pragma unroll
    for (int i = 0; i < CH; i++) { int idx = base + i; if (idx < NN) sum += g_cnt[idx]; }
    s[t] = sum;
    __syncthreads();
    for (int off = 1; off < 1024; off <<= 1) {
        int v = (t >= off) ? s[t - off] : 0;
        __syncthreads();
        s[t] += v;
        __syncthreads();
    }
    int run = (t > 0) ? s[t - 1] : 0;
    #pragma unroll
    for (int i = 0; i < CH; i++) {
        int idx = base + i;
        if (idx < NN) {
            g_rowptr[idx] = run;
            g_cur[idx]    = run;
            int c = g_cnt[idx];
            run += c;
            g_dinv[idx] = rsqrtf(1.0f + (float)c);
        }
    }
    if (t == 1023) g_rowptr[NN] = s[1023];
}

// ---------------- fill CSR + weight split (merged: independent work) -------------
// blocks [0, 1250): edge fill; blocks [1250, 1762): WT1; blocks [1762, 2018): WT2.
__global__ void k_fill_split(const int* __restrict__ src, const int* __restrict__ dst,
                             const float* __restrict__ W1a, const float* __restrict__ W1s,
                             const float* __restrict__ W2a, const float* __restrict__ W2s)
{
    int b = blockIdx.x;
    int k = threadIdx.x;   // 0..255
    if (b < 1250) {
        int e = b * 256 + k;
        if (e < NE) {
            int d = dst[e];
            int pos = atomicAdd(&g_cur[d], 1);
            g_col[pos] = src[e];
        }
    } else if (b < 1762) {
        if (k >= 128) return;
        int n = b - 1250;   // 0..511
        const float* W = (n < 256) ? W1a : W1s;
        int col = n & 255;
        float v = W[k * 256 + col];
        __nv_bfloat16 hi = __float2bfloat16(v);
        __nv_bfloat16 lo = __float2bfloat16(v - __bfloat162float(hi));
        g_WT1[(size_t)n * 384 + k]       = hi;
        g_WT1[(size_t)n * 384 + 128 + k] = hi;
        g_WT1[(size_t)n * 384 + 256 + k] = lo;
    } else {
        int n = (b - 1762) & 127;
        int which = (b - 1762) >> 7;   // 0: W2a, 1: W2s
        const float* W = which ? W2s : W2a;
        __nv_bfloat16* dstp = which ? g_WT2s : g_WT2a;
        float v = W[k * 128 + n];
        __nv_bfloat16 hi = __float2bfloat16(v);
        __nv_bfloat16 lo = __float2bfloat16(v - __bfloat162float(hi));
        dstp[(size_t)n * 768 + k]       = hi;
        dstp[(size_t)n * 768 + 256 + k] = hi;
        dstp[(size_t)n * 768 + 512 + k] = lo;
    }
}

// ---------------- split helpers ----------------
struct alignas(8) bf4 { __nv_bfloat162 a, b; };

__device__ __forceinline__ void split4(float4 v, bf4& hv, bf4& lv) {
    __nv_bfloat16 h0 = __float2bfloat16(v.x), h1 = __float2bfloat16(v.y);
    __nv_bfloat16 h2 = __float2bfloat16(v.z), h3 = __float2bfloat16(v.w);
    __nv_bfloat16 l0 = __float2bfloat16(v.x - __bfloat162float(h0));
    __nv_bfloat16 l1 = __float2bfloat16(v.y - __bfloat162float(h1));
    __nv_bfloat16 l2 = __float2bfloat16(v.z - __bfloat162float(h2));
    __nv_bfloat16 l3 = __float2bfloat16(v.w - __bfloat162float(h3));
    hv.a = __nv_bfloat162(h0, h1); hv.b = __nv_bfloat162(h2, h3);
    lv.a = __nv_bfloat162(l0, l1); lv.b = __nv_bfloat162(l2, l3);
}

__device__ __forceinline__ void split2(float v0, float v1, uint32_t& hi, uint32_t& lo) {
    __nv_bfloat16 h0 = __float2bfloat16(v0), h1 = __float2bfloat16(v1);
    __nv_bfloat16 l0 = __float2bfloat16(v0 - __bfloat162float(h0));
    __nv_bfloat16 l1 = __float2bfloat16(v1 - __bfloat162float(h1));
    __nv_bfloat162 hp(h0, h1), lp(l0, l1);
    hi = *(uint32_t*)&hp; lo = *(uint32_t*)&lp;
}

// ---------------- layer-1 aggregation of RAW features ---------------------------
__global__ void k_agg_h(const float4* __restrict__ h4) {
    int n = blockIdx.x * 4 + (threadIdx.x >> 5);
    if (n >= NN) return;
    int t = threadIdx.x & 31;
    float di = g_dinv[n];
    float4 x = h4[(size_t)n * 32 + t];
    float w0 = di * di;
    float4 a0 = make_float4(x.x * w0, x.y * w0, x.z * w0, x.w * w0);
    float4 a1 = make_float4(0.f, 0.f, 0.f, 0.f);
    float4 a2 = make_float4(0.f, 0.f, 0.f, 0.f);
    float4 a3 = make_float4(0.f, 0.f, 0.f, 0.f);

    int e0 = g_rowptr[n], e1 = g_rowptr[n + 1];
    int e = e0;
    for (; e + 4 <= e1; e += 4) {
        int s0 = g_col[e], s1 = g_col[e + 1], s2 = g_col[e + 2], s3 = g_col[e + 3];
        float ws0 = g_dinv[s0] * di, ws1 = g_dinv[s1] * di;
        float ws2 = g_dinv[s2] * di, ws3 = g_dinv[s3] * di;
        float4 v0 = h4[(size_t)s0 * 32 + t];
        float4 v1 = h4[(size_t)s1 * 32 + t];
        float4 v2 = h4[(size_t)s2 * 32 + t];
        float4 v3 = h4[(size_t)s3 * 32 + t];
        a0.x += v0.x * ws0; a0.y += v0.y * ws0; a0.z += v0.z * ws0; a0.w += v0.w * ws0;
        a1.x += v1.x * ws1; a1.y += v1.y * ws1; a1.z += v1.z * ws1; a1.w += v1.w * ws1;
        a2.x += v2.x * ws2; a2.y += v2.y * ws2; a2.z += v2.z * ws2; a2.w += v2.w * ws2;
        a3.x += v3.x * ws3; a3.y += v3.y * ws3; a3.z += v3.z * ws3; a3.w += v3.w * ws3;
    }
    for (; e < e1; e++) {
        int s = g_col[e];
        float ws = g_dinv[s] * di;
        float4 v = h4[(size_t)s * 32 + t];
        a0.x += v.x * ws; a0.y += v.y * ws; a0.z += v.z * ws; a0.w += v.w * ws;
    }
    float4 acc = make_float4(a0.x + a1.x + a2.x + a3.x, a0.y + a1.y + a2.y + a3.y,
                             a0.z + a1.z + a2.z + a3.z, a0.w + a1.w + a2.w + a3.w);
    bf4 hv, lv; split4(acc, hv, lv);
    int c = t * 4;
    *(bf4*)&g_A1[(size_t)n * 384 + c]       = hv;
    *(bf4*)&g_A1[(size_t)n * 384 + 128 + c] = lv;
    *(bf4*)&g_A1[(size_t)n * 384 + 256 + c] = hv;
}

// ---------------- GCN aggregation layer 2 ----------------------------------------
__global__ void k_agg2(const float4* __restrict__ XW4,   // [NN][64] float4 (F2=256)
                       float* __restrict__ xout,          // [NN][128]
                       __nv_bfloat16* __restrict__ Hb,    // [NN][256] hi|lo
                       const float* __restrict__ b2a, const float* __restrict__ b2s)
{
    int n = blockIdx.x * 2 + (threadIdx.x >> 6);
    if (n >= NN) return;
    int t = threadIdx.x & 63;
    float di = g_dinv[n];
    float4 x = XW4[(size_t)n * 64 + t];
    float w0 = di * di;
    float4 a0 = make_float4(x.x * w0, x.y * w0, x.z * w0, x.w * w0);
    float4 a1 = make_float4(0.f, 0.f, 0.f, 0.f);
    float4 a2 = make_float4(0.f, 0.f, 0.f, 0.f);
    float4 a3 = make_float4(0.f, 0.f, 0.f, 0.f);

    int e0 = g_rowptr[n], e1 = g_rowptr[n + 1];
    int e = e0;
    for (; e + 4 <= e1; e += 4) {
        int s0 = g_col[e], s1 = g_col[e + 1], s2 = g_col[e + 2], s3 = g_col[e + 3];
        float ws0 = g_dinv[s0] * di, ws1 = g_dinv[s1] * di;
        float ws2 = g_dinv[s2] * di, ws3 = g_dinv[s3] * di;
        float4 v0 = XW4[(size_t)s0 * 64 + t];
        float4 v1 = XW4[(size_t)s1 * 64 + t];
        float4 v2 = XW4[(size_t)s2 * 64 + t];
        float4 v3 = XW4[(size_t)s3 * 64 + t];
        a0.x += v0.x * ws0; a0.y += v0.y * ws0; a0.z += v0.z * ws0; a0.w += v0.w * ws0;
        a1.x += v1.x * ws1; a1.y += v1.y * ws1; a1.z += v1.z * ws1; a1.w += v1.w * ws1;
        a2.x += v2.x * ws2; a2.y += v2.y * ws2; a2.z += v2.z * ws2; a2.w += v2.w * ws2;
        a3.x += v3.x * ws3; a3.y += v3.y * ws3; a3.z += v3.z * ws3; a3.w += v3.w * ws3;
    }
    for (; e < e1; e++) {
        int s = g_col[e];
        float ws = g_dinv[s] * di;
        float4 v = XW4[(size_t)s * 64 + t];
        a0.x += v.x * ws; a0.y += v.y * ws; a0.z += v.z * ws; a0.w += v.w * ws;
    }
    float4 acc = make_float4(a0.x + a1.x + a2.x + a3.x, a0.y + a1.y + a2.y + a3.y,
                             a0.z + a1.z + a2.z + a3.z, a0.w + a1.w + a2.w + a3.w);

    int c = t * 4;
    if (c < 128) {
        float4 bv = *(const float4*)&b2a[c];
        acc.x += bv.x; acc.y += bv.y; acc.z += bv.z; acc.w += bv.w;
        *(float4*)&xout[(size_t)n * 128 + c] = acc;
    } else {
        int cc = c - 128;
        float4 bv = *(const float4*)&b2s[cc];
        acc.x += bv.x; acc.y += bv.y; acc.z += bv.z; acc.w += bv.w;
        bf4 hv, lv; split4(acc, hv, lv);
        *(bf4*)&Hb[(size_t)n * 256 + cc]       = hv;
        *(bf4*)&Hb[(size_t)n * 256 + 128 + cc] = lv;
    }
}

// ---------------- bf16 tensor-core GEMM, M=64 tiles, 3 CTA/SM ----------------------
// C[M,N] = A[M,K] @ B[N,K]^T. 64x128 block tile, 8 warps (2x4, warp tile 32x32),
// BK=32, 3-stage cp.async, one barrier per chunk.
// MODE 0: dual-branch (blockIdx.x selects {A,B,coff}); fp32 store.
// MODE 1: bias + relu + bf16 [hi|lo|hi] split-write into g_A2a / g_A2s.
#define BK 32
#define SP 40
#define A_STG (64 * SP)
#define B_STG (128 * SP)
#define GEMM_SMEM (3 * (A_STG + B_STG) * 2)   // 46080 bytes, 3/SM = 135 KB

template <int MODE>
__global__ void __launch_bounds__(256, 3)
gemm_bf(const __nv_bfloat16* __restrict__ A, const __nv_bfloat16* __restrict__ B,
        const __nv_bfloat16* __restrict__ A2, const __nv_bfloat16* __restrict__ B2,
        int K, float* __restrict__ C, int ldc, int M,
        const float* __restrict__ bias_a, const float* __restrict__ bias_s)
{
    extern __shared__ __align__(16) __nv_bfloat16 smem[];
    __nv_bfloat16* As = smem;                 // [3][A_STG]
    __nv_bfloat16* Bs = smem + 3 * A_STG;     // [3][B_STG]

    const int tid  = threadIdx.x;
    const int m0   = blockIdx.y * 64;
    const __nv_bfloat16* Ap = A;
    const __nv_bfloat16* Bp = B;
    int n0, coff;
    if (MODE == 0) {
        if (blockIdx.x) { Ap = A2; Bp = B2; }
        n0 = 0; coff = blockIdx.x * 128;
    } else {
        n0 = blockIdx.x * 128; coff = 0;
    }
    const int w    = tid >> 5;
    const int lane = tid & 31;
    const int wm   = w >> 2;   // 0..1 (32 rows each)
    const int wn   = w & 3;    // 0..3 (32 cols each)
    const int nch  = K / BK;

    float acc[2][4][4];
    #pragma unroll
    for (int mt = 0; mt < 2; mt++)
        #pragma unroll
        for (int nt = 0; nt < 4; nt++)
            #pragma unroll
            for (int i = 0; i < 4; i++) acc[mt][nt][i] = 0.0f;

    auto load_stage = [&](int kc, int st) {
        // A: 64 rows x 4 chunks = 256 (one per thread)
        {
            int r = tid >> 2, q = tid & 3;
            int grow = m0 + r;
            int rg = grow < M ? grow : M - 1;
            const __nv_bfloat16* src = Ap + (size_t)rg * K + kc * BK + q * 8;
            uint32_t dst = (uint32_t)__cvta_generic_to_shared(&As[st * A_STG + r * SP + q * 8]);
            asm volatile("cp.async.cg.shared.global [%0], [%1], 16;\n"
                         :: "r"(dst), "l"(src));
        }
        // B: 128 rows x 4 chunks = 512 (two per thread)
        #pragma unroll
        for (int i = 0; i < 2; i++) {
            int c = tid + i * 256;
            int r = c >> 2, q = c & 3;
            const __nv_bfloat16* src = Bp + (size_t)(n0 + r) * K + kc * BK + q * 8;
            uint32_t dst = (uint32_t)__cvta_generic_to_shared(&Bs[st * B_STG + r * SP + q * 8]);
            asm volatile("cp.async.cg.shared.global [%0], [%1], 16;\n"
                         :: "r"(dst), "l"(src));
        }
    };

    auto compute = [&](int st) {
        #pragma unroll
        for (int ks = 0; ks < 2; ks++) {
            uint32_t a[2][4];
            #pragma unroll
            for (int mt = 0; mt < 2; mt++) {
                int row = wm * 32 + mt * 16 + (lane & 15);
                int col = ks * 16 + ((lane >> 4) << 3);
                uint32_t ad = (uint32_t)__cvta_generic_to_shared(&As[st * A_STG + row * SP + col]);
                asm volatile("ldmatrix.sync.aligned.m8n8.x4.shared.b16 {%0,%1,%2,%3}, [%4];"
                             : "=r"(a[mt][0]), "=r"(a[mt][1]), "=r"(a[mt][2]), "=r"(a[mt][3])
                             : "r"(ad));
            }
            uint32_t b[2][4];
            #pragma unroll
            for (int p = 0; p < 2; p++) {
                int j = lane >> 3, l = lane & 7;
                int row = wn * 32 + p * 16 + ((j >> 1) << 3) + l;
                int col = ks * 16 + ((j & 1) << 3);
                uint32_t bd = (uint32_t)__cvta_generic_to_shared(&Bs[st * B_STG + row * SP + col]);
                asm volatile("ldmatrix.sync.aligned.m8n8.x4.shared.b16 {%0,%1,%2,%3}, [%4];"
                             : "=r"(b[p][0]), "=r"(b[p][1]), "=r"(b[p][2]), "=r"(b[p][3])
                             : "r"(bd));
            }
            #pragma unroll
            for (int mt = 0; mt < 2; mt++)
                #pragma unroll
                for (int nt = 0; nt < 4; nt++) {
                    uint32_t b0 = b[nt >> 1][(nt & 1) * 2];
                    uint32_t b1 = b[nt >> 1][(nt & 1) * 2 + 1];
                    asm volatile(
                        "mma.sync.aligned.m16n8k16.row.col.f32.bf16.bf16.f32 "
                        "{%0,%1,%2,%3}, {%4,%5,%6,%7}, {%8,%9}, {%0,%1,%2,%3};"
                        : "+f"(acc[mt][nt][0]), "+f"(acc[mt][nt][1]),
                          "+f"(acc[mt][nt][2]), "+f"(acc[mt][nt][3])
                        : "r"(a[mt][0]), "r"(a[mt][1]), "r"(a[mt][2]), "r"(a[mt][3]),
                          "r"(b0), "r"(b1));
                }
        }
    };

    load_stage(0, 0);
    asm volatile("cp.async.commit_group;");
    load_stage(1, 1);
    asm volatile("cp.async.commit_group;");

    #pragma unroll 1
    for (int kc = 0; kc < nch; kc++) {
        asm volatile("cp.async.wait_group 1;");
        __syncthreads();
        if (kc + 2 < nch) {
            load_stage(kc + 2, (kc + 2) % 3);
            asm volatile("cp.async.commit_group;");
        } else {
            asm volatile("cp.async.commit_group;");
        }
        compute(kc % 3);
    }

    #pragma unroll
    for (int mt = 0; mt < 2; mt++)
        #pragma unroll
        for (int nt = 0; nt < 4; nt++) {
            int row = m0 + wm * 32 + mt * 16 + (lane >> 2);
            int col = n0 + wn * 32 + nt * 8 + (lane & 3) * 2;
            if (MODE == 0) {
                if (row < M)
                    *(float2*)&C[(size_t)row * ldc + coff + col] =
                        make_float2(acc[mt][nt][0], acc[mt][nt][1]);
                if (row + 8 < M)
                    *(float2*)&C[(size_t)(row + 8) * ldc + coff + col] =
                        make_float2(acc[mt][nt][2], acc[mt][nt][3]);
            } else {
                const float* bias = (col < 256) ? bias_a : bias_s;
                __nv_bfloat16* dst = (col < 256) ? g_A2a : g_A2s;
                int lc = col & 255;
                float bv0 = bias[lc], bv1 = bias[lc + 1];
                #pragma unroll
                for (int half = 0; half < 2; half++) {
                    int r = row + half * 8;
                    if (r < M) {
                        float v0 = fmaxf(acc[mt][nt][half * 2]     + bv0, 0.f);
                        float v1 = fmaxf(acc[mt][nt][half * 2 + 1] + bv1, 0.f);
                        uint32_t hi, lo; split2(v0, v1, hi, lo);
                        *(uint32_t*)&dst[(size_t)r * 768 + lc]       = hi;
                        *(uint32_t*)&dst[(size_t)r * 768 + 256 + lc] = lo;
                        *(uint32_t*)&dst[(size_t)r * 768 + 512 + lc] = hi;
                    }
                }
            }
        }
}

// ---------------- Gram via bf16 tensor cores (mma.sync), SYMMETRIC -----------------
// 128x128 tiles, BK=64, 2-stage pipeline, 2 CTA/SM, single-pass transpose epilogue.
#define NT 79
#define NTILES (NT * (NT + 1) / 2)  // 3160
#define GBK 64
#define GSP 72                      // pitch: 64 bf16 + 8 pad (144B rows)
#define G_STG (128 * GSP)
#define GRAM_SMEM (2 * 2 * G_STG * 2)   // 73728 bytes
#define TP 130                      // full-tile transpose staging pitch (floats)

__global__ void __launch_bounds__(256, 2)
gram_mma(const __nv_bfloat16* __restrict__ Hb, float* __restrict__ C)
{
    extern __shared__ __align__(16) __nv_bfloat16 smem[];
    __nv_bfloat16* As = smem;                 // [2][G_STG]
    __nv_bfloat16* Bs = smem + 2 * G_STG;     // [2][G_STG]
    float* sT = (float*)smem;                 // reused after mainloop: [128][TP]

    // ---- map linear tile id -> (ti, tj) with ti <= tj ----
    int t = blockIdx.x;
    int ti = (int)((2.0f * NT + 1.0f -
                    sqrtf((2.0f * NT + 1.0f) * (2.0f * NT + 1.0f) - 8.0f * (float)t)) * 0.5f);
    if (ti < 0) ti = 0;
    if (ti > NT - 1) ti = NT - 1;
    #pragma unroll 1
    while (ti > 0 && (ti * NT - ti * (ti - 1) / 2) > t) ti--;
    #pragma unroll 1
    while (ti < NT - 1 && ((ti + 1) * NT - (ti + 1) * ti / 2) <= t) ti++;
    const int tj = ti + (t - (ti * NT - ti * (ti - 1) / 2));

    const int m0 = ti * 128;
    const int n0 = tj * 128;

    const int tid  = threadIdx.x;
    const int w    = tid >> 5;
    const int lane = tid & 31;
    const int wm   = w >> 2;
    const int wn   = w & 3;

    float acc[4][4][4];
    #pragma unroll
    for (int mt = 0; mt < 4; mt++)
        #pragma unroll
        for (int nt = 0; nt < 4; nt++)
            #pragma unroll
            for (int i = 0; i < 4; i++) acc[mt][nt][i] = 0.0f;

    auto load_stage = [&](int kc, int st) {
        #pragma unroll
        for (int i = 0; i < 4; i++) {
            int c = tid + i * 256;            // 0..1023
            int r = c >> 3, q = c & 7;
            {
                int grow = m0 + r;
                int rg = grow < NN ? grow : NN - 1;
                const __nv_bfloat16* src = Hb + (size_t)rg * 256 + kc * GBK + q * 8;
                uint32_t dst = (uint32_t)__cvta_generic_to_shared(&As[st * G_STG + r * GSP + q * 8]);
                asm volatile("cp.async.cg.shared.global [%0], [%1], 16;\n"
                             :: "r"(dst), "l"(src));
            }
            {
                int grow = n0 + r;
                int rg = grow < NN ? grow : NN - 1;
                const __nv_bfloat16* src = Hb + (size_t)rg * 256 + kc * GBK + q * 8;
                uint32_t dst = (uint32_t)__cvta_generic_to_shared(&Bs[st * G_STG + r * GSP + q * 8]);
                asm volatile("cp.async.cg.shared.global [%0], [%1], 16;\n"
                             :: "r"(dst), "l"(src));
            }
        }
    };

    auto compute = [&](int st) {
        #pragma unroll
        for (int ks = 0; ks < 4; ks++) {
            uint32_t a[4][4];
            #pragma unroll
            for (int mt = 0; mt < 4; mt++) {
                int row = wm * 64 + mt * 16 + (lane & 15);
                int col = ks * 16 + ((lane >> 4) << 3);
                uint32_t ad = (uint32_t)__cvta_generic_to_shared(&As[st * G_STG + row * GSP + col]);
                asm volatile("ldmatrix.sync.aligned.m8n8.x4.shared.b16 {%0,%1,%2,%3}, [%4];"
                             : "=r"(a[mt][0]), "=r"(a[mt][1]), "=r"(a[mt][2]), "=r"(a[mt][3])
                             : "r"(ad));
            }
            uint32_t b[2][4];
            #pragma unroll
            for (int p = 0; p < 2; p++) {
                int j = lane >> 3, l = lane & 7;
                int row = wn * 32 + p * 16 + ((j >> 1) << 3) + l;
                int col = ks * 16 + ((j & 1) << 3);
                uint32_t bd = (uint32_t)__cvta_generic_to_shared(&Bs[st * G_STG + row * GSP + col]);
                asm volatile("ldmatrix.sync.aligned.m8n8.x4.shared.b16 {%0,%1,%2,%3}, [%4];"
                             : "=r"(b[p][0]), "=r"(b[p][1]), "=r"(b[p][2]), "=r"(b[p][3])
                             : "r"(bd));
            }
            #pragma unroll
            for (int mt = 0; mt < 4; mt++)
                #pragma unroll
                for (int nt = 0; nt < 4; nt++) {
                    uint32_t b0 = b[nt >> 1][(nt & 1) * 2];
                    uint32_t b1 = b[nt >> 1][(nt & 1) * 2 + 1];
                    asm volatile(
                        "mma.sync.aligned.m16n8k16.row.col.f32.bf16.bf16.f32 "
                        "{%0,%1,%2,%3}, {%4,%5,%6,%7}, {%8,%9}, {%0,%1,%2,%3};"
                        : "+f"(acc[mt][nt][0]), "+f"(acc[mt][nt][1]),
                          "+f"(acc[mt][nt][2]), "+f"(acc[mt][nt][3])
                        : "r"(a[mt][0]), "r"(a[mt][1]), "r"(a[mt][2]), "r"(a[mt][3]),
                          "r"(b0), "r"(b1));
                }
        }
    };

    // double-buffered mainloop over 4 chunks
    load_stage(0, 0);
    asm volatile("cp.async.commit_group;");

    #pragma unroll 1
    for (int kc = 0; kc < 4; kc++) {
        if (kc + 1 < 4) {
            load_stage(kc + 1, (kc + 1) & 1);
            asm volatile("cp.async.commit_group;");
            asm volatile("cp.async.wait_group 1;");
        } else {
            asm volatile("cp.async.wait_group 0;");
        }
        __syncthreads();
        compute(kc & 1);
        __syncthreads();
    }

    // ---- direct write: C[m0 + rows, n0 + cols] ----
    #pragma unroll
    for (int mt = 0; mt < 4; mt++)
        #pragma unroll
        for (int nt = 0; nt < 4; nt++) {
            int row = m0 + wm * 64 + mt * 16 + (lane >> 2);
            int col = n0 + wn * 32 + nt * 8 + (lane & 3) * 2;
            if (col < NN) {
                if (row < NN)
                    *(float2*)&C[(size_t)row * NN + col] =
                        make_float2(acc[mt][nt][0], acc[mt][nt][1]);
                if (row + 8 < NN)
                    *(float2*)&C[(size_t)(row + 8) * NN + col] =
                        make_float2(acc[mt][nt][2], acc[mt][nt][3]);
            }
        }

    // ---- transposed write for off-diagonal tiles: single full-tile staging ----
    if (ti != tj) {
        __syncthreads();
        #pragma unroll
        for (int mt = 0; mt < 4; mt++) {
            int rloc = wm * 64 + mt * 16 + (lane >> 2);   // 0..127
            #pragma unroll
            for (int nt = 0; nt < 4; nt++) {
                int cloc = wn * 32 + nt * 8 + (lane & 3) * 2;
                sT[(cloc)     * TP + rloc]     = acc[mt][nt][0];
                sT[(cloc + 1) * TP + rloc]     = acc[mt][nt][1];
                sT[(cloc)     * TP + rloc + 8] = acc[mt][nt][2];
                sT[(cloc + 1) * TP + rloc + 8] = acc[mt][nt][3];
            }
        }
        __syncthreads();
        #pragma unroll
        for (int e = 0; e < 16; e++) {
            int idx = tid + 256 * e;       // 0..4095
            int cc  = idx >> 5;            // 0..127
            int rr  = (idx & 31) * 4;      // 0..124
            int grow = n0 + cc;
            int gcol = m0 + rr;
            if (grow < NN) {
                float4 v = make_float4(sT[cc * TP + rr],
                                       sT[cc * TP + rr + 1],
                                       sT[cc * TP + rr + 2],
                                       sT[cc * TP + rr + 3]);
                if (gcol + 3 < NN) {
                    *(float4*)&C[(size_t)grow * NN + gcol] = v;
                } else {
                    float vv[4] = {v.x, v.y, v.z, v.w};
                    #pragma unroll
                    for (int k = 0; k < 4; k++)
                        if (gcol + k < NN) C[(size_t)grow * NN + gcol + k] = vv[k];
                }
            }
        }
    }
}

// ---------------- launcher ----------------
extern "C" void kernel_launch(void* const* d_in, const int* in_sizes, int n_in,
                              void* d_out, int out_size)
{
    const float* h   = (const float*)d_in[0];
    const float* W1a = (const float*)d_in[1];
    const float* b1a = (const float*)d_in[2];
    const float* W2a = (const float*)d_in[3];
    const float* b2a = (const float*)d_in[4];
    const float* W1s = (const float*)d_in[5];
    const float* b1s = (const float*)d_in[6];
    const float* W2s = (const float*)d_in[7];
    const float* b2s = (const float*)d_in[8];
    const int*   ei  = (const int*)d_in[9];
    const int* src = ei;
    const int* dst = ei + NE;
    float* out = (float*)d_out;

    float* pXW2;
    __nv_bfloat16 *pHb, *pA1, *pA2a, *pA2s, *pWT1, *pWT2a, *pWT2s;
    int* pCnt;
    cudaGetSymbolAddress((void**)&pXW2,  g_XW2);
    cudaGetSymbolAddress((void**)&pHb,   g_Hb);
    cudaGetSymbolAddress((void**)&pA1,   g_A1);
    cudaGetSymbolAddress((void**)&pA2a,  g_A2a);
    cudaGetSymbolAddress((void**)&pA2s,  g_A2s);
    cudaGetSymbolAddress((void**)&pWT1,  g_WT1);
    cudaGetSymbolAddress((void**)&pWT2a, g_WT2a);
    cudaGetSymbolAddress((void**)&pWT2s, g_WT2s);
    cudaGetSymbolAddress((void**)&pCnt,  g_cnt);

    cudaFuncSetAttribute(gram_mma,   cudaFuncAttributeMaxDynamicSharedMemorySize, GRAM_SMEM);
    cudaFuncSetAttribute(gemm_bf<0>, cudaFuncAttributeMaxDynamicSharedMemorySize, GEMM_SMEM);
    cudaFuncSetAttribute(gemm_bf<1>, cudaFuncAttributeMaxDynamicSharedMemorySize, GEMM_SMEM);

    const int MT64 = (NN + 63) / 64;   // 157 M-tiles of 64 rows

    // graph prep (+ weight conversion merged into fill launch)
    cudaMemsetAsync(pCnt, 0, NN * sizeof(int));
    k_count<<<(NE + 255) / 256, 256>>>(dst);
    k_scan <<<1, 1024>>>();
    k_fill_split<<<1250 + 512 + 256, 256>>>(src, dst, W1a, W1s, W2a, W2s);

    // layer 1 (aggregate-first): hagg = A_norm@h -> A1; H1 = relu(hagg@W1+b) -> A2a/A2s
    k_agg_h<<<(NN + 3) / 4, 128>>>((const float4*)h);
    gemm_bf<1><<<dim3(4, MT64), 256, GEMM_SMEM>>>(pA1, pWT1, nullptr, nullptr, 384,
                                                  nullptr, 0, NN, b1a, b1s);

    // layer 2 (transform-first), both branches in ONE launch
    gemm_bf<0><<<dim3(2, MT64), 256, GEMM_SMEM>>>(pA2a, pWT2a, pA2s, pWT2s, 768,
                                                  pXW2, 256, NN, nullptr, nullptr);
    k_agg2<<<(NN + 1) / 2, 128>>>((const float4*)pXW2, out, pHb, b2a, b2s);

    // s_ = h_ @ h_^T: symmetric 128x128 tiles, BK=64, double-buffered
    gram_mma<<<NTILES, 256, GRAM_SMEM>>>(pHb, out + S_OFF);

    // h passthrough
    cudaMemcpyAsync(out + H_OFF, h, (size_t)NN * 128 * sizeof(float),
                    cudaMemcpyDeviceToDevice);
}